// round 7
// baseline (speedup 1.0000x reference)
#include <cuda_runtime.h>
#include <cstdint>
#include <cfloat>
#include <math.h>

typedef unsigned long long u64;

#define DHALF 64
#define DFULL 128
#define KCODES 512
#define MTILE 64
#define ZS_STRIDE 66   // float2 per z row (padded for bank-conflict-free LDS)

// Scratch accumulators (device globals: allocation-free per harness rules)
__device__ float g_nt[KCODES];
__device__ float g_dw[KCODES * DFULL];
__device__ float g_ysq[KCODES];

__device__ __forceinline__ u64 fma2(u64 a, u64 b, u64 c) {
    u64 d;
    asm("fma.rn.f32x2 %0, %1, %2, %3;" : "=l"(d) : "l"(a), "l"(b), "l"(c));
    return d;
}

// ---------------------------------------------------------------------------
// Stage 0: y_sq[k] = sum_j w[k][j]^2, zero count + dw accumulators.
// ---------------------------------------------------------------------------
__global__ void vq_prep(const float* __restrict__ emb) {
    int k = blockIdx.x * blockDim.x + threadIdx.x;
    if (k < KCODES) {
        const float* w = emb + (size_t)k * DFULL;
        float s = 0.f;
        #pragma unroll 8
        for (int d = 0; d < DFULL; d++) s = __fadd_rn(s, __fmul_rn(w[d], w[d]));
        g_ysq[k] = s;
        g_nt[k] = 0.f;
        #pragma unroll 8
        for (int d = 0; d < DFULL; d++) g_dw[(size_t)k * DFULL + d] = 0.f;
    }
}

// ---------------------------------------------------------------------------
// Stage 1: per-row argmin over 512 codes (f32x2 register-tiled GEMM),
// then per-row outputs (indices, loss, straight-through zq) + atomic
// accumulation of counts and dw segment sums.
// Block: 256 threads = 16(tx along k) x 16(ty along m). Tile: 64 rows.
// ---------------------------------------------------------------------------
__global__ void __launch_bounds__(256, 2)
vq_main(const float* __restrict__ zr, const float* __restrict__ zi,
        const float* __restrict__ emb,
        float* __restrict__ o_zqr, float* __restrict__ o_zqi,
        float* __restrict__ o_loss, float* __restrict__ o_idx)
{
    extern __shared__ char sm[];
    float2* zs    = (float2*)sm;                                   // [64][66]
    float2* wst   = (float2*)(sm + MTILE * ZS_STRIDE * 8);         // [64][128] (dpair-major)
    float*  ysq_s = (float*)(sm + MTILE * ZS_STRIDE * 8 + 64 * 128 * 8); // [128]
    float*  xsq_s = ysq_s + 128;                                   // [64]
    int*    resk  = (int*)(xsq_s + MTILE);                         // [64]

    const int tid  = threadIdx.x;
    const int row0 = blockIdx.x * MTILE;

    // Load z tile: 64 rows x 128 floats (real[0:64] ++ imag[0:64]), coalesced.
    for (int i = tid; i < MTILE * 32; i += 256) {
        int row = i >> 5, q = i & 31;
        const float* src = (q < 16) ? (zr + (size_t)(row0 + row) * DHALF + q * 4)
                                    : (zi + (size_t)(row0 + row) * DHALF + (q - 16) * 4);
        float4 v = *(const float4*)src;
        float2* dst = &zs[row * ZS_STRIDE + q * 2];
        dst[0] = make_float2(v.x, v.y);
        dst[1] = make_float2(v.z, v.w);
    }
    __syncthreads();

    // x_sq per row (sequential fp32, no fma-contraction: square then add)
    if (tid < MTILE) {
        const float* zrow = (const float*)&zs[tid * ZS_STRIDE];
        float s = 0.f;
        #pragma unroll 8
        for (int d = 0; d < DFULL; d++) s = __fadd_rn(s, __fmul_rn(zrow[d], zrow[d]));
        xsq_s[tid] = s;
    }

    const int tx = tid & 15, ty = tid >> 4;
    float bestv[4]; int bestk[4];
    #pragma unroll
    for (int i = 0; i < 4; i++) { bestv[i] = FLT_MAX; bestk[i] = 0; }

    const u64* za = reinterpret_cast<const u64*>(zs) + ty * 4 * ZS_STRIDE;

    for (int c = 0; c < 4; c++) {
        __syncthreads();  // protect wst reuse across chunks
        // Load 128-code chunk transposed: wst[r][k] = (w[k][2r], w[k][2r+1])
        for (int i = tid; i < 64 * 128; i += 256) {
            int r = i >> 7, k = i & 127;
            wst[r * 128 + k] = *(const float2*)(emb + (size_t)(c * 128 + k) * DFULL + r * 2);
        }
        if (tid < 128) ysq_s[tid] = g_ysq[c * 128 + tid];
        __syncthreads();

        u64 acc[4][8];
        #pragma unroll
        for (int i = 0; i < 4; i++)
            #pragma unroll
            for (int j = 0; j < 8; j++) acc[i][j] = 0ull;

        const u64* wa = reinterpret_cast<const u64*>(wst) + tx;
        #pragma unroll 4
        for (int r = 0; r < 64; r++) {
            u64 a0 = za[r];
            u64 a1 = za[r +     ZS_STRIDE];
            u64 a2 = za[r + 2 * ZS_STRIDE];
            u64 a3 = za[r + 3 * ZS_STRIDE];
            const u64* wr = wa + r * 128;
            #pragma unroll
            for (int j = 0; j < 8; j++) {
                u64 b = wr[j * 16];
                acc[0][j] = fma2(a0, b, acc[0][j]);
                acc[1][j] = fma2(a1, b, acc[1][j]);
                acc[2][j] = fma2(a2, b, acc[2][j]);
                acc[3][j] = fma2(a3, b, acc[3][j]);
            }
        }

        // Chunk epilogue: dist = fl(fl(x_sq + y_sq) - 2*dot), strict-< scan
        // (k ascending across c then j -> first-min kept, matching jnp.argmin)
        #pragma unroll
        for (int i = 0; i < 4; i++) {
            float xs = xsq_s[ty * 4 + i];
            #pragma unroll
            for (int j = 0; j < 8; j++) {
                float lo = __uint_as_float((unsigned)(acc[i][j] & 0xffffffffull));
                float hi = __uint_as_float((unsigned)(acc[i][j] >> 32));
                float dot = __fadd_rn(lo, hi);
                float s = __fadd_rn(xs, ysq_s[j * 16 + tx]);
                float dist = __fmaf_rn(-2.0f, dot, s);  // == fl(s - fl(2*dot)), 2*dot exact
                if (dist < bestv[i]) { bestv[i] = dist; bestk[i] = c * 128 + j * 16 + tx; }
            }
        }
    }

    // Cross-tx argmin reduction (16 lanes), tie -> smaller index
    #pragma unroll
    for (int i = 0; i < 4; i++) {
        float v = bestv[i]; int k = bestk[i];
        #pragma unroll
        for (int off = 8; off; off >>= 1) {
            float ov = __shfl_xor_sync(0xffffffffu, v, off);
            int   ok = __shfl_xor_sync(0xffffffffu, k, off);
            if (ov < v || (ov == v && ok < k)) { v = ov; k = ok; }
        }
        if (tx == 0) resk[ty * 4 + i] = k;
    }
    __syncthreads();

    // Phase 2: per-row outputs + segment accumulation. 4 threads per row.
    {
        int row = tid >> 2, part = tid & 3;
        size_t n = (size_t)row0 + row;
        int idx = resk[row];
        const float* wp  = emb + (size_t)idx * DFULL + part * 32;
        const float* zp  = (const float*)&zs[row * ZS_STRIDE] + part * 32;
        float*       dwp = g_dw + (size_t)idx * DFULL + part * 32;
        float* oz = (part < 2) ? (o_zqr + n * DHALF + part * 32)
                               : (o_zqi + n * DHALF + (part - 2) * 32);
        float ls = 0.f;
        #pragma unroll
        for (int q = 0; q < 8; q++) {
            float4 o;
            #pragma unroll
            for (int e = 0; e < 4; e++) {
                float zv = zp[q * 4 + e];
                float wv = __ldg(wp + q * 4 + e);
                float dv = __fsub_rn(wv, zv);
                ls = __fadd_rn(ls, __fmul_rn(dv, dv));
                (&o.x)[e] = __fadd_rn(zv, dv);   // z + (z_q - z): straight-through rounding
                atomicAdd(dwp + q * 4 + e, zv);
            }
            *(float4*)(oz + q * 4) = o;
        }
        ls = __fadd_rn(ls, __shfl_xor_sync(0xffffffffu, ls, 1));
        ls = __fadd_rn(ls, __shfl_xor_sync(0xffffffffu, ls, 2));
        if (part == 0) {
            o_loss[n] = __fmul_rn(0.25f, __fmul_rn(ls, (1.0f / 128.0f)));  // BETA * mean
            o_idx[n]  = (float)idx;
            atomicAdd(&g_nt[idx], 1.0f);
        }
    }
}

// ---------------------------------------------------------------------------
// Stage 2: EMA update, cluster-size normalization, entropy. 1 block x 512.
// ---------------------------------------------------------------------------
__global__ void vq_final(const float* __restrict__ ecs, const float* __restrict__ emaw,
                         float* __restrict__ o_ent, float* __restrict__ o_emb,
                         float* __restrict__ o_nc,  float* __restrict__ o_ema)
{
    __shared__ float red[512];
    int k = threadIdx.x;
    const float DEC = 0.99f;
    const float OM  = (float)(1.0 - 0.99);

    float ntv = g_nt[k];
    float nc  = __fadd_rn(__fmul_rn(ecs[k], DEC), __fmul_rn(OM, ntv));
    o_nc[k] = nc;

    red[k] = nc;
    __syncthreads();
    for (int s = 256; s > 0; s >>= 1) {
        if (k < s) red[k] = __fadd_rn(red[k], red[k + s]);
        __syncthreads();
    }
    float tot = red[0];
    __syncthreads();

    float csz = __fmul_rn(__fdiv_rn(__fadd_rn(nc, 1e-5f),
                                    __fadd_rn(tot, (float)(512 * 1e-5))), tot);

    for (int d = 0; d < DFULL; d++) {
        float ne = __fadd_rn(__fmul_rn(emaw[(size_t)k * DFULL + d], DEC),
                             __fmul_rn(OM, g_dw[(size_t)k * DFULL + d]));
        o_ema[(size_t)k * DFULL + d] = ne;
        o_emb[(size_t)k * DFULL + d] = __fdiv_rn(ne, csz);
    }

    float p = __fdiv_rn(ntv, 262144.0f);
    float t = __fmul_rn(p, logf(__fadd_rn(p, 1e-10f)));
    red[k] = t;
    __syncthreads();
    for (int s = 256; s > 0; s >>= 1) {
        if (k < s) red[k] = __fadd_rn(red[k], red[k + s]);
        __syncthreads();
    }
    if (k == 0) o_ent[0] = __fdiv_rn(-red[0], 6.2383246250395075f);  // / log(512)
}

// ---------------------------------------------------------------------------
extern "C" void kernel_launch(void* const* d_in, const int* in_sizes, int n_in,
                              void* d_out, int out_size)
{
    const float* zr   = (const float*)d_in[0];
    const float* zi   = (const float*)d_in[1];
    const float* emb  = (const float*)d_in[2];
    const float* ecs  = (const float*)d_in[3];
    const float* emaw = (const float*)d_in[4];
    float* out = (float*)d_out;

    size_t nrows = (size_t)in_sizes[0] / DHALF;   // 262144

    // Output layout = reference return tuple, flattened + concatenated
    float* o_zqr  = out;
    float* o_zqi  = o_zqr + nrows * DHALF;
    float* o_loss = o_zqi + nrows * DHALF;
    float* o_idx  = o_loss + nrows;
    float* o_ent  = o_idx + nrows;
    float* o_emb  = o_ent + 1;
    float* o_nc   = o_emb + (size_t)KCODES * DFULL;
    float* o_ema  = o_nc + KCODES;

    vq_prep<<<2, 256>>>(emb);

    const size_t smem = MTILE * ZS_STRIDE * 8   // zs
                      + 64 * 128 * 8            // wst
                      + 128 * 4                 // ysq_s
                      + MTILE * 4               // xsq_s
                      + MTILE * 4;              // resk
    cudaFuncSetAttribute(vq_main, cudaFuncAttributeMaxDynamicSharedMemorySize, (int)smem);
    vq_main<<<(unsigned)(nrows / MTILE), 256, smem>>>(zr, zi, emb,
                                                      o_zqr, o_zqi, o_loss, o_idx);

    vq_final<<<1, 512>>>(ecs, emaw, o_ent, o_emb, o_nc, o_ema);
}

// round 8
// speedup vs baseline: 1.0024x; 1.0024x over previous
#include <cuda_runtime.h>
#include <cstdint>
#include <cfloat>
#include <math.h>

typedef unsigned long long u64;

#define DHALF 64
#define DFULL 128
#define KCODES 512
#define MTILE 64
#define ZS_STRIDE 66   // float2 per z row (padded for bank-conflict-free LDS)

// Scratch accumulators (device globals: allocation-free per harness rules)
__device__ float g_nt[KCODES];
__device__ float g_dw[KCODES * DFULL];
__device__ float g_ysq[KCODES];

__device__ __forceinline__ u64 fma2(u64 a, u64 b, u64 c) {
    u64 d;
    asm("fma.rn.f32x2 %0, %1, %2, %3;" : "=l"(d) : "l"(a), "l"(b), "l"(c));
    return d;
}

// ---------------------------------------------------------------------------
// Stage 0: y_sq[k] = sum_j w[k][j]^2, zero count + dw accumulators.
// ---------------------------------------------------------------------------
__global__ void vq_prep(const float* __restrict__ emb) {
    int k = blockIdx.x * blockDim.x + threadIdx.x;
    if (k < KCODES) {
        const float* w = emb + (size_t)k * DFULL;
        float s = 0.f;
        #pragma unroll 8
        for (int d = 0; d < DFULL; d++) s = __fadd_rn(s, __fmul_rn(w[d], w[d]));
        g_ysq[k] = s;
        g_nt[k] = 0.f;
        #pragma unroll 8
        for (int d = 0; d < DFULL; d++) g_dw[(size_t)k * DFULL + d] = 0.f;
    }
}

// ---------------------------------------------------------------------------
// Stage 1: per-row argmin over 512 codes (f32x2 register-tiled GEMM),
// then per-row outputs (indices, loss, straight-through zq) + atomic
// accumulation of counts and dw segment sums.
// Block: 256 threads = 16(tx along k) x 16(ty along m). Tile: 64 rows.
// ---------------------------------------------------------------------------
__global__ void __launch_bounds__(256, 2)
vq_main(const float* __restrict__ zr, const float* __restrict__ zi,
        const float* __restrict__ emb,
        float* __restrict__ o_zqr, float* __restrict__ o_zqi,
        float* __restrict__ o_loss, float* __restrict__ o_idx)
{
    extern __shared__ char sm[];
    float2* zs    = (float2*)sm;                                   // [64][66]
    float2* wst   = (float2*)(sm + MTILE * ZS_STRIDE * 8);         // [64][128] (dpair-major)
    float*  ysq_s = (float*)(sm + MTILE * ZS_STRIDE * 8 + 64 * 128 * 8); // [128]
    float*  xsq_s = ysq_s + 128;                                   // [64]
    int*    resk  = (int*)(xsq_s + MTILE);                         // [64]

    const int tid  = threadIdx.x;
    const int row0 = blockIdx.x * MTILE;

    // Load z tile: 64 rows x 128 floats (real[0:64] ++ imag[0:64]), coalesced.
    for (int i = tid; i < MTILE * 32; i += 256) {
        int row = i >> 5, q = i & 31;
        const float* src = (q < 16) ? (zr + (size_t)(row0 + row) * DHALF + q * 4)
                                    : (zi + (size_t)(row0 + row) * DHALF + (q - 16) * 4);
        float4 v = *(const float4*)src;
        float2* dst = &zs[row * ZS_STRIDE + q * 2];
        dst[0] = make_float2(v.x, v.y);
        dst[1] = make_float2(v.z, v.w);
    }
    __syncthreads();

    // x_sq per row (sequential fp32, no fma-contraction: square then add)
    if (tid < MTILE) {
        const float* zrow = (const float*)&zs[tid * ZS_STRIDE];
        float s = 0.f;
        #pragma unroll 8
        for (int d = 0; d < DFULL; d++) s = __fadd_rn(s, __fmul_rn(zrow[d], zrow[d]));
        xsq_s[tid] = s;
    }

    const int tx = tid & 15, ty = tid >> 4;
    float bestv[4]; int bestk[4];
    #pragma unroll
    for (int i = 0; i < 4; i++) { bestv[i] = FLT_MAX; bestk[i] = 0; }

    const u64* za = reinterpret_cast<const u64*>(zs) + ty * 4 * ZS_STRIDE;

    for (int c = 0; c < 4; c++) {
        __syncthreads();  // protect wst reuse across chunks
        // Load 128-code chunk transposed: wst[r][k] = (w[k][2r], w[k][2r+1])
        for (int i = tid; i < 64 * 128; i += 256) {
            int r = i >> 7, k = i & 127;
            wst[r * 128 + k] = *(const float2*)(emb + (size_t)(c * 128 + k) * DFULL + r * 2);
        }
        if (tid < 128) ysq_s[tid] = g_ysq[c * 128 + tid];
        __syncthreads();

        u64 acc[4][8];
        #pragma unroll
        for (int i = 0; i < 4; i++)
            #pragma unroll
            for (int j = 0; j < 8; j++) acc[i][j] = 0ull;

        const u64* wa = reinterpret_cast<const u64*>(wst) + tx;
        #pragma unroll 4
        for (int r = 0; r < 64; r++) {
            u64 a0 = za[r];
            u64 a1 = za[r +     ZS_STRIDE];
            u64 a2 = za[r + 2 * ZS_STRIDE];
            u64 a3 = za[r + 3 * ZS_STRIDE];
            const u64* wr = wa + r * 128;
            #pragma unroll
            for (int j = 0; j < 8; j++) {
                u64 b = wr[j * 16];
                acc[0][j] = fma2(a0, b, acc[0][j]);
                acc[1][j] = fma2(a1, b, acc[1][j]);
                acc[2][j] = fma2(a2, b, acc[2][j]);
                acc[3][j] = fma2(a3, b, acc[3][j]);
            }
        }

        // Chunk epilogue: dist = fl(fl(x_sq + y_sq) - 2*dot), strict-< scan
        // (k ascending across c then j -> first-min kept, matching jnp.argmin)
        #pragma unroll
        for (int i = 0; i < 4; i++) {
            float xs = xsq_s[ty * 4 + i];
            #pragma unroll
            for (int j = 0; j < 8; j++) {
                float lo = __uint_as_float((unsigned)(acc[i][j] & 0xffffffffull));
                float hi = __uint_as_float((unsigned)(acc[i][j] >> 32));
                float dot = __fadd_rn(lo, hi);
                float s = __fadd_rn(xs, ysq_s[j * 16 + tx]);
                float dist = __fmaf_rn(-2.0f, dot, s);  // == fl(s - fl(2*dot)), 2*dot exact
                if (dist < bestv[i]) { bestv[i] = dist; bestk[i] = c * 128 + j * 16 + tx; }
            }
        }
    }

    // Cross-tx argmin reduction (16 lanes), tie -> smaller index
    #pragma unroll
    for (int i = 0; i < 4; i++) {
        float v = bestv[i]; int k = bestk[i];
        #pragma unroll
        for (int off = 8; off; off >>= 1) {
            float ov = __shfl_xor_sync(0xffffffffu, v, off);
            int   ok = __shfl_xor_sync(0xffffffffu, k, off);
            if (ov < v || (ov == v && ok < k)) { v = ov; k = ok; }
        }
        if (tx == 0) resk[ty * 4 + i] = k;
    }
    __syncthreads();

    // Phase 2: per-row outputs + segment accumulation. 4 threads per row.
    {
        int row = tid >> 2, part = tid & 3;
        size_t n = (size_t)row0 + row;
        int idx = resk[row];
        const float* wp  = emb + (size_t)idx * DFULL + part * 32;
        const float* zp  = (const float*)&zs[row * ZS_STRIDE] + part * 32;
        float*       dwp = g_dw + (size_t)idx * DFULL + part * 32;
        float* oz = (part < 2) ? (o_zqr + n * DHALF + part * 32)
                               : (o_zqi + n * DHALF + (part - 2) * 32);
        float ls = 0.f;
        #pragma unroll
        for (int q = 0; q < 8; q++) {
            float4 o;
            #pragma unroll
            for (int e = 0; e < 4; e++) {
                float zv = zp[q * 4 + e];
                float wv = __ldg(wp + q * 4 + e);
                float dv = __fsub_rn(wv, zv);
                ls = __fadd_rn(ls, __fmul_rn(dv, dv));
                (&o.x)[e] = __fadd_rn(zv, dv);   // z + (z_q - z): straight-through rounding
                atomicAdd(dwp + q * 4 + e, zv);
            }
            *(float4*)(oz + q * 4) = o;
        }
        ls = __fadd_rn(ls, __shfl_xor_sync(0xffffffffu, ls, 1));
        ls = __fadd_rn(ls, __shfl_xor_sync(0xffffffffu, ls, 2));
        if (part == 0) {
            o_loss[n] = __fmul_rn(0.25f, __fmul_rn(ls, (1.0f / 128.0f)));  // BETA * mean
            o_idx[n]  = (float)idx;
            atomicAdd(&g_nt[idx], 1.0f);
        }
    }
}

// ---------------------------------------------------------------------------
// Stage 2: EMA update, cluster-size normalization, entropy. 1 block x 512.
// ---------------------------------------------------------------------------
__global__ void vq_final(const float* __restrict__ ecs, const float* __restrict__ emaw,
                         float* __restrict__ o_ent, float* __restrict__ o_emb,
                         float* __restrict__ o_nc,  float* __restrict__ o_ema)
{
    __shared__ float red[512];
    int k = threadIdx.x;
    const float DEC = 0.99f;
    const float OM  = (float)(1.0 - 0.99);

    float ntv = g_nt[k];
    float nc  = __fadd_rn(__fmul_rn(ecs[k], DEC), __fmul_rn(OM, ntv));
    o_nc[k] = nc;

    red[k] = nc;
    __syncthreads();
    for (int s = 256; s > 0; s >>= 1) {
        if (k < s) red[k] = __fadd_rn(red[k], red[k + s]);
        __syncthreads();
    }
    float tot = red[0];
    __syncthreads();

    float csz = __fmul_rn(__fdiv_rn(__fadd_rn(nc, 1e-5f),
                                    __fadd_rn(tot, (float)(512 * 1e-5))), tot);

    for (int d = 0; d < DFULL; d++) {
        float ne = __fadd_rn(__fmul_rn(emaw[(size_t)k * DFULL + d], DEC),
                             __fmul_rn(OM, g_dw[(size_t)k * DFULL + d]));
        o_ema[(size_t)k * DFULL + d] = ne;
        o_emb[(size_t)k * DFULL + d] = __fdiv_rn(ne, csz);
    }

    float p = __fdiv_rn(ntv, 262144.0f);
    float t = __fmul_rn(p, logf(__fadd_rn(p, 1e-10f)));
    red[k] = t;
    __syncthreads();
    for (int s = 256; s > 0; s >>= 1) {
        if (k < s) red[k] = __fadd_rn(red[k], red[k + s]);
        __syncthreads();
    }
    if (k == 0) o_ent[0] = __fdiv_rn(-red[0], 6.2383246250395075f);  // / log(512)
}

// ---------------------------------------------------------------------------
extern "C" void kernel_launch(void* const* d_in, const int* in_sizes, int n_in,
                              void* d_out, int out_size)
{
    const float* zr   = (const float*)d_in[0];
    const float* zi   = (const float*)d_in[1];
    const float* emb  = (const float*)d_in[2];
    const float* ecs  = (const float*)d_in[3];
    const float* emaw = (const float*)d_in[4];
    float* out = (float*)d_out;

    size_t nrows = (size_t)in_sizes[0] / DHALF;   // 262144

    // Output layout = reference return tuple, flattened + concatenated
    float* o_zqr  = out;
    float* o_zqi  = o_zqr + nrows * DHALF;
    float* o_loss = o_zqi + nrows * DHALF;
    float* o_idx  = o_loss + nrows;
    float* o_ent  = o_idx + nrows;
    float* o_emb  = o_ent + 1;
    float* o_nc   = o_emb + (size_t)KCODES * DFULL;
    float* o_ema  = o_nc + KCODES;

    vq_prep<<<2, 256>>>(emb);

    const size_t smem = MTILE * ZS_STRIDE * 8   // zs
                      + 64 * 128 * 8            // wst
                      + 128 * 4                 // ysq_s
                      + MTILE * 4               // xsq_s
                      + MTILE * 4;              // resk
    cudaFuncSetAttribute(vq_main, cudaFuncAttributeMaxDynamicSharedMemorySize, (int)smem);
    vq_main<<<(unsigned)(nrows / MTILE), 256, smem>>>(zr, zi, emb,
                                                      o_zqr, o_zqi, o_loss, o_idx);

    vq_final<<<1, 512>>>(ecs, emaw, o_ent, o_emb, o_nc, o_ema);
}

// round 13
// speedup vs baseline: 1.0621x; 1.0595x over previous
#include <cuda_runtime.h>
#include <cuda_bf16.h>
#include <cstdint>
#include <cfloat>
#include <math.h>

typedef unsigned long long u64;
typedef unsigned int u32;

#define DHALF 64
#define DFULL 128
#define KCODES 512
#define MTILE 128
#define NTHREADS 512

// Device-global scratch (allocation-free per harness rules)
__device__ float g_nt[KCODES];
__device__ float g_dw[KCODES * DFULL];
__device__ float g_ysq[KCODES];
__device__ __nv_bfloat16 g_bs[2 * KCODES * DFULL];   // 2 bf16 splits of codebook

// ---------------------------------------------------------------------------
// Warp-level tensor-core primitives (plain sm_80+ PTX; compute_103-safe —
// tcgen05.* is rejected by the harness's ptxas target)
// ---------------------------------------------------------------------------
__device__ __forceinline__ u32 smem_u32(const void* p) {
    u32 a;
    asm("{ .reg .u64 t; cvta.to.shared.u64 t, %1; cvt.u32.u64 %0, t; }"
        : "=r"(a) : "l"(p));
    return a;
}

#define LDSM_X4(r, addr) \
    asm volatile("ldmatrix.sync.aligned.m8n8.x4.shared.b16 {%0,%1,%2,%3}, [%4];" \
                 : "=r"((r)[0]), "=r"((r)[1]), "=r"((r)[2]), "=r"((r)[3]) \
                 : "r"(addr))

#define LDSM_X2(r, addr) \
    asm volatile("ldmatrix.sync.aligned.m8n8.x2.shared.b16 {%0,%1}, [%2];" \
                 : "=r"((r)[0]), "=r"((r)[1]) : "r"(addr))

#define MMA16816(d, a, b) \
    asm volatile("mma.sync.aligned.m16n8k16.row.col.f32.bf16.bf16.f32 " \
                 "{%0,%1,%2,%3},{%4,%5,%6,%7},{%8,%9},{%0,%1,%2,%3};" \
                 : "+f"((d)[0]), "+f"((d)[1]), "+f"((d)[2]), "+f"((d)[3]) \
                 : "r"((a)[0]), "r"((a)[1]), "r"((a)[2]), "r"((a)[3]), \
                   "r"((b)[0]), "r"((b)[1]))

#define REDG_V4(ptr, v) \
    asm volatile("red.global.add.v4.f32 [%0], {%1,%2,%3,%4};" \
                 :: "l"(ptr), "f"((v).x), "f"((v).y), "f"((v).z), "f"((v).w) \
                 : "memory")

// Total-order packing: (dist, idx) -> u64, ascending compare == lexicographic
__device__ __forceinline__ u64 pack_di(float dist, int idx) {
    u32 fb = __float_as_uint(dist);
    u32 key = ((int)fb < 0) ? ~fb : (fb | 0x80000000u);
    return ((u64)key << 32) | (u32)idx;
}
__device__ __forceinline__ float unpack_d(u64 p) {
    u32 k = (u32)(p >> 32);
    u32 fb = (k & 0x80000000u) ? (k ^ 0x80000000u) : ~k;
    return __uint_as_float(fb);
}
// Insert into ascending-sorted triple
__device__ __forceinline__ void ins3(u64* t, u64 x) {
    if (x < t[0])      { t[2] = t[1]; t[1] = t[0]; t[0] = x; }
    else if (x < t[1]) { t[2] = t[1]; t[1] = x; }
    else if (x < t[2]) { t[2] = x; }
}

// ---------------------------------------------------------------------------
// Stage 0: y_sq (reference fp32 order), zero accumulators, 2-way bf16 split
// of the codebook. grid = 512 blocks x 128 threads.
// ---------------------------------------------------------------------------
__global__ void vq_prep(const float* __restrict__ emb) {
    int b = blockIdx.x, t = threadIdx.x;
    float f = emb[(size_t)b * DFULL + t];
    __nv_bfloat16 h0 = __float2bfloat16(f);
    float r1 = __fsub_rn(f, __bfloat162float(h0));
    __nv_bfloat16 h1 = __float2bfloat16(r1);
    size_t e = (size_t)b * DFULL + t;
    g_bs[0 * KCODES * DFULL + e] = h0;
    g_bs[1 * KCODES * DFULL + e] = h1;
    g_dw[e] = 0.f;
    if (t == 0) {
        g_nt[b] = 0.f;
        const float* w = emb + (size_t)b * DFULL;
        float s = 0.f;
        #pragma unroll 8
        for (int d = 0; d < DFULL; d++) s = __fadd_rn(s, __fmul_rn(w[d], w[d]));
        g_ysq[b] = s;
    }
}

// ---------------------------------------------------------------------------
// Smem layout. A/B tiles in 8x8-atom layout: atom (r8, k8) of a 128x128 bf16
// tile at ((r8*16 + k8)*128) bytes; its 8 rows at consecutive 16B slots ->
// conflict-free ldmatrix.
// ---------------------------------------------------------------------------
static constexpr int SM_TOP3 = 0;        // 128 rows x 4 quads x 3 u64 = 12288
static constexpr int SM_XSQ  = 12288;    // 128 f32
static constexpr int SM_YSQ  = 12800;    // 512 f32
static constexpr int SM_RESK = 14848;    // 128 int
static constexpr int SM_A    = 16384;    // 2 splits x 32768
static constexpr int SM_B    = 81920;    // 2 splits x 32768
static constexpr int SM_TOTAL = 147456;

// ---------------------------------------------------------------------------
// Stage 1: 3-term Ozaki HMMA distance GEMM -> per-quadrant top-3 candidates
// -> exact fp32 rescore (near-tie rows only) -> outputs + segment sums.
// One CTA per 128-row tile; 512 threads = 16 warps (4m x 4n), 32x32 tiles.
// ---------------------------------------------------------------------------
__global__ void __launch_bounds__(NTHREADS, 1)
vq_main(const float* __restrict__ zr, const float* __restrict__ zi,
        const float* __restrict__ emb,
        float* __restrict__ o_zqr, float* __restrict__ o_zqi,
        float* __restrict__ o_loss, float* __restrict__ o_idx)
{
    extern __shared__ char sm[];
    const u32 smb = smem_u32(sm);
    const int tid  = threadIdx.x;
    const int wid  = tid >> 5, lane = tid & 31;
    const int wm   = wid & 3,  wn   = wid >> 2;
    const int row0 = blockIdx.x * MTILE;

    u64*   top3  = (u64*)(sm + SM_TOP3);
    float* xsq_s = (float*)(sm + SM_XSQ);
    float* ysq_s = (float*)(sm + SM_YSQ);
    int*   resk  = (int*)(sm + SM_RESK);

    for (int i = tid; i < 128 * 4 * 3; i += NTHREADS) top3[i] = ~0ull;
    if (tid < KCODES) ysq_s[tid] = g_ysq[tid];

    // A tile: z rows (real -> k 0-63, imag -> k 64-127), 2-way bf16 split,
    // atom-layout stores.
    for (int i = tid; i < MTILE * 32; i += NTHREADS) {
        int row = i >> 5, q = i & 31;
        const float* src = (q < 16) ? (zr + (size_t)(row0 + row) * DHALF + q * 4)
                                    : (zi + (size_t)(row0 + row) * DHALF + (q - 16) * 4);
        float4 v = *(const float4*)src;
        u32 off = (u32)(((row >> 3) * 16 + (q >> 1)) * 128 + (row & 7) * 16 + (q & 1) * 8);
        unsigned short hs[2][4];
        #pragma unroll
        for (int e2 = 0; e2 < 4; e2++) {
            float f = (&v.x)[e2];
            __nv_bfloat16 h0 = __float2bfloat16(f);
            float r1 = __fsub_rn(f, __bfloat162float(h0));
            __nv_bfloat16 h1 = __float2bfloat16(r1);
            hs[0][e2] = __bfloat16_as_ushort(h0);
            hs[1][e2] = __bfloat16_as_ushort(h1);
        }
        #pragma unroll
        for (int s = 0; s < 2; s++) {
            u64 w = (u64)hs[s][0] | ((u64)hs[s][1] << 16)
                  | ((u64)hs[s][2] << 32) | ((u64)hs[s][3] << 48);
            *(u64*)(sm + SM_A + s * 32768 + off) = w;
        }
    }

    // x_sq per row: sequential fp32 in reference order (real then imag)
    if (tid < MTILE) {
        const float* a = zr + (size_t)(row0 + tid) * DHALF;
        const float* b = zi + (size_t)(row0 + tid) * DHALF;
        float s = 0.f;
        #pragma unroll 8
        for (int d = 0; d < DHALF; d++) s = __fadd_rn(s, __fmul_rn(a[d], a[d]));
        #pragma unroll 8
        for (int d = 0; d < DHALF; d++) s = __fadd_rn(s, __fmul_rn(b[d], b[d]));
        xsq_s[tid] = s;
    }

    // Per-lane ldmatrix offsets
    const int g = lane >> 3, rr = lane & 7;
    const u32 aoff = (u32)((g & 1) * 2048 + (g >> 1) * 128 + rr * 16);
    const int lb = lane & 15;
    const u32 boff = (u32)((lb >> 3) * 128 + (lb & 7) * 16);
    const int l4 = lane >> 2, lc = (lane & 3) * 2;

    // Ozaki term schedule: {a0b0, a0b1, a1b0}; a1b1 (~2e-6 on dist) omitted —
    // decisions near ties are made by the exact rescore below.
    const int SA[3] = {0, 0, 1};
    const int SB[3] = {0, 1, 0};

    for (int c = 0; c < 4; c++) {
        __syncthreads();   // prior chunk's LDSM done before B overwrite

        // Load B chunk: 2 splits x 128 codes x 128 bf16, atom layout
        for (int i = tid; i < 2 * 128 * 16; i += NTHREADS) {
            int s   = i >> 11;
            int r   = (i >> 4) & 127;
            int k16 = i & 15;
            const uint4 v = *(const uint4*)((const char*)g_bs
                + ((size_t)s * KCODES * DFULL + (size_t)(c * 128 + r) * DFULL
                   + (size_t)k16 * 8) * 2);
            *(uint4*)(sm + SM_B + s * 32768
                      + ((r >> 3) * 16 + k16) * 128 + (r & 7) * 16) = v;
        }
        __syncthreads();

        float d[2][4][4];
        #pragma unroll
        for (int mt = 0; mt < 2; mt++)
            #pragma unroll
            for (int nt = 0; nt < 4; nt++)
                #pragma unroll
                for (int e2 = 0; e2 < 4; e2++) d[mt][nt][e2] = 0.f;

        #pragma unroll
        for (int s3 = 0; s3 < 3; s3++) {
            const u32 Ab = smb + SM_A + SA[s3] * 32768 + wm * 8192 + aoff;
            const u32 Bb = smb + SM_B + SB[s3] * 32768 + wn * 8192 + boff;
            #pragma unroll
            for (int ks = 0; ks < 8; ks++) {
                u32 a[2][4], bb[4][2];
                LDSM_X4(a[0], Ab + ks * 256);
                LDSM_X4(a[1], Ab + 4096 + ks * 256);
                #pragma unroll
                for (int nt = 0; nt < 4; nt++)
                    LDSM_X2(bb[nt], Bb + nt * 2048 + ks * 256);
                #pragma unroll
                for (int mt = 0; mt < 2; mt++)
                    #pragma unroll
                    for (int nt = 0; nt < 4; nt++)
                        MMA16816(d[mt][nt], a[mt], bb[nt]);
            }
        }

        // Chunk epilogue: approx dist -> per-(row, quadrant) top-3.
        #pragma unroll
        for (int mt = 0; mt < 2; mt++) {
            #pragma unroll
            for (int rh = 0; rh < 2; rh++) {
                int row = wm * 32 + mt * 16 + rh * 8 + l4;
                float xs = xsq_s[row];
                u64 t[3] = {~0ull, ~0ull, ~0ull};
                #pragma unroll
                for (int nt = 0; nt < 4; nt++) {
                    #pragma unroll
                    for (int cl = 0; cl < 2; cl++) {
                        int code = c * 128 + wn * 32 + nt * 8 + lc + cl;
                        float dist = __fmaf_rn(-2.0f, d[mt][nt][rh * 2 + cl],
                                               __fadd_rn(xs, ysq_s[code]));
                        ins3(t, pack_di(dist, code));
                    }
                }
                #pragma unroll
                for (int off = 1; off <= 2; off <<= 1) {
                    u64 o0 = __shfl_xor_sync(0xffffffffu, t[0], off);
                    u64 o1 = __shfl_xor_sync(0xffffffffu, t[1], off);
                    u64 o2 = __shfl_xor_sync(0xffffffffu, t[2], off);
                    ins3(t, o0); ins3(t, o1); ins3(t, o2);
                }
                if ((lane & 3) == 0) {   // single owner per slot -> race-free
                    u64* slot = &top3[(row * 4 + wn) * 3];
                    ins3(t, slot[0]); ins3(t, slot[1]); ins3(t, slot[2]);
                    slot[0] = t[0]; slot[1] = t[1]; slot[2] = t[2];
                }
            }
        }
    }
    __syncthreads();

    // Decision phase: 4 threads per row. Accept the approx winner only when
    // the approx top-2 gap exceeds 1e-3 — 150x the worst-case filter error
    // (~6e-6: omitted a1b1 + HMMA accumulation rounding), so acceptance is
    // provably exact. Otherwise (~20% of rows) rescore all 12 candidates in
    // exact fp32 and take the lexicographic (dist, idx) min == jnp.argmin
    // first-min semantics.
    {
        int row = tid >> 2, part = tid & 3;
        size_t n = (size_t)row0 + row;
        u64* slot = top3 + row * 12;
        u64 c0 = ~0ull, c1 = ~0ull;
        int cidx[12];
        #pragma unroll
        for (int i = 0; i < 12; i++) {
            u64 x = slot[i];
            cidx[i] = (int)(u32)x;
            if (x < c0) { c1 = c0; c0 = x; }
            else if (x < c1) c1 = x;
        }
        int widx;
        if (__fsub_rn(unpack_d(c1), unpack_d(c0)) > 1e-3f) {
            widx = (int)(u32)c0;
        } else {
            const u32 gmask = 0xFu << (lane & 28);
            const float* zp = (part < 2) ? (zr + n * DHALF + part * 32)
                                         : (zi + n * DHALF + (part - 2) * 32);
            float acc[12];
            #pragma unroll
            for (int i = 0; i < 12; i++) acc[i] = 0.f;
            for (int dd = 0; dd < 32; dd++) {
                float zv = __ldg(zp + dd);
                #pragma unroll
                for (int i = 0; i < 12; i++)
                    acc[i] = __fmaf_rn(zv,
                        __ldg(emb + (size_t)cidx[i] * DFULL + part * 32 + dd),
                        acc[i]);
            }
            #pragma unroll
            for (int off = 1; off <= 2; off <<= 1)
                #pragma unroll
                for (int i = 0; i < 12; i++)
                    acc[i] = __fadd_rn(acc[i],
                                       __shfl_xor_sync(gmask, acc[i], off));
            float xs = xsq_s[row];
            u64 bp = ~0ull;
            #pragma unroll
            for (int i = 0; i < 12; i++) {
                float dist = __fmaf_rn(-2.0f, acc[i],
                                       __fadd_rn(xs, ysq_s[cidx[i]]));
                u64 p = pack_di(dist, cidx[i]);
                if (p < bp) bp = p;
            }
            widx = (int)(u32)bp;
        }
        if (part == 0) resk[row] = widx;
    }
    __syncthreads();

    // Phase 2: per-row outputs + segment accumulation. 4 threads per row.
    {
        int row = tid >> 2, part = tid & 3;
        size_t n = (size_t)row0 + row;
        int idx = resk[row];
        const float* wp  = emb + (size_t)idx * DFULL + part * 32;
        const float* zp  = (part < 2) ? (zr + n * DHALF + part * 32)
                                      : (zi + n * DHALF + (part - 2) * 32);
        float* dwp = g_dw + (size_t)idx * DFULL + part * 32;
        float* oz  = (part < 2) ? (o_zqr + n * DHALF + part * 32)
                                : (o_zqi + n * DHALF + (part - 2) * 32);
        float ls = 0.f;
        #pragma unroll
        for (int q = 0; q < 8; q++) {
            float4 zv4 = *(const float4*)(zp + q * 4);
            float4 o;
            #pragma unroll
            for (int e2 = 0; e2 < 4; e2++) {
                float zv = (&zv4.x)[e2];
                float wv = __ldg(wp + q * 4 + e2);
                float dv = __fsub_rn(wv, zv);
                ls = __fadd_rn(ls, __fmul_rn(dv, dv));
                (&o.x)[e2] = __fadd_rn(zv, dv);   // z + (z_q - z): straight-through
            }
            REDG_V4(dwp + q * 4, zv4);
            *(float4*)(oz + q * 4) = o;
        }
        ls = __fadd_rn(ls, __shfl_xor_sync(0xffffffffu, ls, 1));
        ls = __fadd_rn(ls, __shfl_xor_sync(0xffffffffu, ls, 2));
        if (part == 0) {
            o_loss[n] = __fmul_rn(0.25f, __fmul_rn(ls, (1.0f / 128.0f)));
            o_idx[n]  = (float)idx;
            atomicAdd(&g_nt[idx], 1.0f);
        }
    }
}

// ---------------------------------------------------------------------------
// Stage 2: EMA update, cluster-size normalization, entropy. 1 block x 512.
// ---------------------------------------------------------------------------
__global__ void vq_final(const float* __restrict__ ecs, const float* __restrict__ emaw,
                         float* __restrict__ o_ent, float* __restrict__ o_emb,
                         float* __restrict__ o_nc,  float* __restrict__ o_ema)
{
    __shared__ float red[512];
    int k = threadIdx.x;
    const float DEC = 0.99f;
    const float OM  = (float)(1.0 - 0.99);

    float ntv = g_nt[k];
    float nc  = __fadd_rn(__fmul_rn(ecs[k], DEC), __fmul_rn(OM, ntv));
    o_nc[k] = nc;

    red[k] = nc;
    __syncthreads();
    for (int s = 256; s > 0; s >>= 1) {
        if (k < s) red[k] = __fadd_rn(red[k], red[k + s]);
        __syncthreads();
    }
    float tot = red[0];
    __syncthreads();

    float csz = __fmul_rn(__fdiv_rn(__fadd_rn(nc, 1e-5f),
                                    __fadd_rn(tot, (float)(512 * 1e-5))), tot);

    for (int d = 0; d < DFULL; d++) {
        float ne = __fadd_rn(__fmul_rn(emaw[(size_t)k * DFULL + d], DEC),
                             __fmul_rn(OM, g_dw[(size_t)k * DFULL + d]));
        o_ema[(size_t)k * DFULL + d] = ne;
        o_emb[(size_t)k * DFULL + d] = __fdiv_rn(ne, csz);
    }

    float p = __fdiv_rn(ntv, 262144.0f);
    float t = __fmul_rn(p, logf(__fadd_rn(p, 1e-10f)));
    red[k] = t;
    __syncthreads();
    for (int s = 256; s > 0; s >>= 1) {
        if (k < s) red[k] = __fadd_rn(red[k], red[k + s]);
        __syncthreads();
    }
    if (k == 0) o_ent[0] = __fdiv_rn(-red[0], 6.2383246250395075f);  // / log(512)
}

// ---------------------------------------------------------------------------
extern "C" void kernel_launch(void* const* d_in, const int* in_sizes, int n_in,
                              void* d_out, int out_size)
{
    const float* zr   = (const float*)d_in[0];
    const float* zi   = (const float*)d_in[1];
    const float* emb  = (const float*)d_in[2];
    const float* ecs  = (const float*)d_in[3];
    const float* emaw = (const float*)d_in[4];
    float* out = (float*)d_out;

    size_t nrows = (size_t)in_sizes[0] / DHALF;   // 262144

    // Output layout = reference return tuple, flattened + concatenated
    float* o_zqr  = out;
    float* o_zqi  = o_zqr + nrows * DHALF;
    float* o_loss = o_zqi + nrows * DHALF;
    float* o_idx  = o_loss + nrows;
    float* o_ent  = o_idx + nrows;
    float* o_emb  = o_ent + 1;
    float* o_nc   = o_emb + (size_t)KCODES * DFULL;
    float* o_ema  = o_nc + KCODES;

    vq_prep<<<KCODES, DFULL>>>(emb);

    cudaFuncSetAttribute(vq_main, cudaFuncAttributeMaxDynamicSharedMemorySize,
                         SM_TOTAL);
    vq_main<<<(unsigned)(nrows / MTILE), NTHREADS, SM_TOTAL>>>(
        zr, zi, emb, o_zqr, o_zqi, o_loss, o_idx);

    vq_final<<<1, 512>>>(ecs, emaw, o_ent, o_emb, o_nc, o_ema);
}

// round 14
// speedup vs baseline: 1.5212x; 1.4324x over previous
#include <cuda_runtime.h>
#include <cuda_fp16.h>
#include <cstdint>
#include <cfloat>
#include <math.h>

typedef unsigned long long u64;
typedef unsigned int u32;

#define DHALF 64
#define DFULL 128
#define KCODES 512
#define MTILE 128
#define NTHREADS 512

// Device-global scratch (allocation-free per harness rules)
__device__ float g_nt[KCODES];
__device__ float g_dw[KCODES * DFULL];
__device__ float g_ysq[KCODES];
__device__ __half g_hw[KCODES * DFULL];   // fp16 codebook, pre-scaled by 512

// ---------------------------------------------------------------------------
// Warp-level primitives (plain sm_80+ PTX; compute_103-safe)
// ---------------------------------------------------------------------------
__device__ __forceinline__ u32 smem_u32(const void* p) {
    u32 a;
    asm("{ .reg .u64 t; cvta.to.shared.u64 t, %1; cvt.u32.u64 %0, t; }"
        : "=r"(a) : "l"(p));
    return a;
}

#define LDSM_X4(r, addr) \
    asm volatile("ldmatrix.sync.aligned.m8n8.x4.shared.b16 {%0,%1,%2,%3}, [%4];" \
                 : "=r"((r)[0]), "=r"((r)[1]), "=r"((r)[2]), "=r"((r)[3]) \
                 : "r"(addr))

#define MMA16816F16(d, a, b0, b1) \
    asm volatile("mma.sync.aligned.m16n8k16.row.col.f32.f16.f16.f32 " \
                 "{%0,%1,%2,%3},{%4,%5,%6,%7},{%8,%9},{%0,%1,%2,%3};" \
                 : "+f"((d)[0]), "+f"((d)[1]), "+f"((d)[2]), "+f"((d)[3]) \
                 : "r"((a)[0]), "r"((a)[1]), "r"((a)[2]), "r"((a)[3]), \
                   "r"(b0), "r"(b1))

#define REDG_V4(ptr, v) \
    asm volatile("red.global.add.v4.f32 [%0], {%1,%2,%3,%4};" \
                 :: "l"(ptr), "f"((v).x), "f"((v).y), "f"((v).z), "f"((v).w) \
                 : "memory")

// Total-order packing: (dist, idx) -> u64, ascending compare == lexicographic
__device__ __forceinline__ u64 pack_di(float dist, int idx) {
    u32 fb = __float_as_uint(dist);
    u32 key = ((int)fb < 0) ? ~fb : (fb | 0x80000000u);
    return ((u64)key << 32) | (u32)idx;
}
__device__ __forceinline__ float unpack_d(u64 p) {
    u32 k = (u32)(p >> 32);
    u32 fb = (k & 0x80000000u) ? (k ^ 0x80000000u) : ~k;
    return __uint_as_float(fb);
}
// Insert into ascending-sorted triple
__device__ __forceinline__ void ins3(u64* t, u64 x) {
    if (x < t[0])      { t[2] = t[1]; t[1] = t[0]; t[0] = x; }
    else if (x < t[1]) { t[2] = t[1]; t[1] = x; }
    else if (x < t[2]) { t[2] = x; }
}

// ---------------------------------------------------------------------------
// Stage 0: y_sq (reference fp32 order), zero accumulators, fp16 codebook
// pre-scaled by 512 (exact pow2; 512*w in (-1,1) -> fp16 rel err 2^-11).
// ---------------------------------------------------------------------------
__global__ void vq_prep(const float* __restrict__ emb) {
    int b = blockIdx.x, t = threadIdx.x;
    size_t e = (size_t)b * DFULL + t;
    float f = emb[e];
    g_hw[e] = __float2half_rn(__fmul_rn(f, 512.0f));
    g_dw[e] = 0.f;
    if (t == 0) {
        g_nt[b] = 0.f;
        const float* w = emb + (size_t)b * DFULL;
        float s = 0.f;
        #pragma unroll 8
        for (int d = 0; d < DFULL; d++) s = __fadd_rn(s, __fmul_rn(w[d], w[d]));
        g_ysq[b] = s;
    }
}

// ---------------------------------------------------------------------------
// Smem layout. A/B tiles in 8x8-atom layout: atom (r8, k8) of a 128x128 fp16
// tile at ((r8*16 + k8)*128) bytes; its 8 rows at consecutive 16B slots ->
// conflict-free ldmatrix.
// ---------------------------------------------------------------------------
static constexpr int SM_TOP3 = 0;        // 128 rows x 4 quads x 3 u64 = 12288
static constexpr int SM_XSQ  = 12288;    // 128 f32
static constexpr int SM_YSQ  = 12800;    // 512 f32
static constexpr int SM_RESK = 14848;    // 128 int
static constexpr int SM_A    = 16384;    // 32768 (128x128 fp16)
static constexpr int SM_B    = 49152;    // 32768 (128-code chunk fp16)
static constexpr int SM_TOTAL = 81920;   // -> 2 CTAs/SM

// ---------------------------------------------------------------------------
// Stage 1: single-term fp16 HMMA filter -> per-quadrant top-3 candidates ->
// exact fp32 rescore (near-tie rows only) -> outputs + segment sums.
// One CTA per 128-row tile; 512 threads = 16 warps (4m x 4n), 32x32 tiles.
// ---------------------------------------------------------------------------
__global__ void __launch_bounds__(NTHREADS, 2)
vq_main(const float* __restrict__ zr, const float* __restrict__ zi,
        const float* __restrict__ emb,
        float* __restrict__ o_zqr, float* __restrict__ o_zqi,
        float* __restrict__ o_loss, float* __restrict__ o_idx)
{
    extern __shared__ char sm[];
    const u32 smb = smem_u32(sm);
    const int tid  = threadIdx.x;
    const int wid  = tid >> 5, lane = tid & 31;
    const int wm   = wid & 3,  wn   = wid >> 2;
    const int row0 = blockIdx.x * MTILE;

    u64*   top3  = (u64*)(sm + SM_TOP3);
    float* xsq_s = (float*)(sm + SM_XSQ);
    float* ysq_s = (float*)(sm + SM_YSQ);
    int*   resk  = (int*)(sm + SM_RESK);

    for (int i = tid; i < 128 * 4 * 3; i += NTHREADS) top3[i] = ~0ull;
    if (tid < KCODES) ysq_s[tid] = g_ysq[tid];

    // A tile: z rows (real -> k 0-63, imag -> k 64-127) as fp16, atom layout.
    for (int i = tid; i < MTILE * 32; i += NTHREADS) {
        int row = i >> 5, q = i & 31;
        const float* src = (q < 16) ? (zr + (size_t)(row0 + row) * DHALF + q * 4)
                                    : (zi + (size_t)(row0 + row) * DHALF + (q - 16) * 4);
        float4 v = *(const float4*)src;
        u32 off = (u32)(((row >> 3) * 16 + (q >> 1)) * 128 + (row & 7) * 16 + (q & 1) * 8);
        unsigned short h[4];
        #pragma unroll
        for (int e2 = 0; e2 < 4; e2++)
            h[e2] = __half_as_ushort(__float2half_rn((&v.x)[e2]));
        *(u64*)(sm + SM_A + off) = (u64)h[0] | ((u64)h[1] << 16)
                                 | ((u64)h[2] << 32) | ((u64)h[3] << 48);
    }

    // x_sq per row: sequential fp32 in reference order (real then imag)
    if (tid < MTILE) {
        const float* a = zr + (size_t)(row0 + tid) * DHALF;
        const float* b = zi + (size_t)(row0 + tid) * DHALF;
        float s = 0.f;
        #pragma unroll 8
        for (int d = 0; d < DHALF; d++) s = __fadd_rn(s, __fmul_rn(a[d], a[d]));
        #pragma unroll 8
        for (int d = 0; d < DHALF; d++) s = __fadd_rn(s, __fmul_rn(b[d], b[d]));
        xsq_s[tid] = s;
    }

    // Per-lane ldmatrix offsets
    const int g = lane >> 3, rr = lane & 7;
    const u32 aoff = (u32)((g & 1) * 2048 + (g >> 1) * 128 + rr * 16);
    // B x4: matrices {0,1} -> n8-tile nt0 (k-even/odd atoms), {2,3} -> nt0+1
    const u32 boff = (u32)((lane >> 4) * 2048 + ((lane >> 3) & 1) * 128 + (lane & 7) * 16);
    const int l4 = lane >> 2, lc = (lane & 3) * 2;

    for (int c = 0; c < 4; c++) {
        __syncthreads();   // prior chunk's LDSM done before B overwrite

        // Load B chunk: 128 codes x 128 fp16 (pre-scaled), atom layout.
        for (int i = tid; i < 128 * 16; i += NTHREADS) {
            int r = i >> 4, k16 = i & 15;
            const uint4 v = *(const uint4*)((const char*)g_hw
                + ((size_t)(c * 128 + r) * DFULL + (size_t)k16 * 8) * 2);
            *(uint4*)(sm + SM_B + ((r >> 3) * 16 + k16) * 128 + (r & 7) * 16) = v;
        }
        __syncthreads();

        float d[2][4][4];
        #pragma unroll
        for (int mt = 0; mt < 2; mt++)
            #pragma unroll
            for (int nt = 0; nt < 4; nt++)
                #pragma unroll
                for (int e2 = 0; e2 < 4; e2++) d[mt][nt][e2] = 0.f;

        const u32 Ab = smb + SM_A + wm * 8192 + aoff;
        const u32 Bb = smb + SM_B + wn * 8192 + boff;
        #pragma unroll
        for (int ks = 0; ks < 8; ks++) {
            u32 a0[4], a1[4], t0[4], t1[4];
            LDSM_X4(a0, Ab + ks * 256);
            LDSM_X4(a1, Ab + 4096 + ks * 256);
            LDSM_X4(t0, Bb + ks * 256);           // nt 0,1
            LDSM_X4(t1, Bb + 4096 + ks * 256);    // nt 2,3
            MMA16816F16(d[0][0], a0, t0[0], t0[1]);
            MMA16816F16(d[0][1], a0, t0[2], t0[3]);
            MMA16816F16(d[0][2], a0, t1[0], t1[1]);
            MMA16816F16(d[0][3], a0, t1[2], t1[3]);
            MMA16816F16(d[1][0], a1, t0[0], t0[1]);
            MMA16816F16(d[1][1], a1, t0[2], t0[3]);
            MMA16816F16(d[1][2], a1, t1[0], t1[1]);
            MMA16816F16(d[1][3], a1, t1[2], t1[3]);
        }

        // Chunk epilogue: approx dist -> per-(row, quadrant) top-3.
        // B was pre-scaled by 512, so -2*dot = -2^-8 * d (exact rescale).
        #pragma unroll
        for (int mt = 0; mt < 2; mt++) {
            #pragma unroll
            for (int rh = 0; rh < 2; rh++) {
                int row = wm * 32 + mt * 16 + rh * 8 + l4;
                float xs = xsq_s[row];
                u64 t[3] = {~0ull, ~0ull, ~0ull};
                #pragma unroll
                for (int nt = 0; nt < 4; nt++) {
                    #pragma unroll
                    for (int cl = 0; cl < 2; cl++) {
                        int code = c * 128 + wn * 32 + nt * 8 + lc + cl;
                        float dist = __fmaf_rn(-0.00390625f, d[mt][nt][rh * 2 + cl],
                                               __fadd_rn(xs, ysq_s[code]));
                        ins3(t, pack_di(dist, code));
                    }
                }
                #pragma unroll
                for (int off = 1; off <= 2; off <<= 1) {
                    u64 o0 = __shfl_xor_sync(0xffffffffu, t[0], off);
                    u64 o1 = __shfl_xor_sync(0xffffffffu, t[1], off);
                    u64 o2 = __shfl_xor_sync(0xffffffffu, t[2], off);
                    ins3(t, o0); ins3(t, o1); ins3(t, o2);
                }
                if ((lane & 3) == 0) {   // single owner per slot -> race-free
                    u64* slot = &top3[(row * 4 + wn) * 3];
                    ins3(t, slot[0]); ins3(t, slot[1]); ins3(t, slot[2]);
                    slot[0] = t[0]; slot[1] = t[1]; slot[2] = t[2];
                }
            }
        }
    }
    __syncthreads();

    // Decision phase: 4 threads per row. Accept the approx winner only when
    // the approx top-2 gap exceeds 1e-3 — ~8x the 5-sigma filter error
    // (fp16 inputs ~2.4e-5 rms on dist), so acceptance is reliable.
    // Otherwise (~20% of rows) rescore all 12 candidates in exact fp32 and
    // take the lexicographic (dist, idx) min == jnp.argmin first-min.
    {
        int row = tid >> 2, part = tid & 3;
        size_t n = (size_t)row0 + row;
        u64* slot = top3 + row * 12;
        u64 c0 = ~0ull, c1 = ~0ull;
        int cidx[12];
        #pragma unroll
        for (int i = 0; i < 12; i++) {
            u64 x = slot[i];
            cidx[i] = (int)(u32)x;
            if (x < c0) { c1 = c0; c0 = x; }
            else if (x < c1) c1 = x;
        }
        int widx;
        if (__fsub_rn(unpack_d(c1), unpack_d(c0)) > 1e-3f) {
            widx = (int)(u32)c0;
        } else {
            const u32 gmask = 0xFu << (lane & 28);
            const float* zp = (part < 2) ? (zr + n * DHALF + part * 32)
                                         : (zi + n * DHALF + (part - 2) * 32);
            float acc[12];
            #pragma unroll
            for (int i = 0; i < 12; i++) acc[i] = 0.f;
            for (int dd = 0; dd < 32; dd++) {
                float zv = __ldg(zp + dd);
                #pragma unroll
                for (int i = 0; i < 12; i++)
                    acc[i] = __fmaf_rn(zv,
                        __ldg(emb + (size_t)cidx[i] * DFULL + part * 32 + dd),
                        acc[i]);
            }
            #pragma unroll
            for (int off = 1; off <= 2; off <<= 1)
                #pragma unroll
                for (int i = 0; i < 12; i++)
                    acc[i] = __fadd_rn(acc[i],
                                       __shfl_xor_sync(gmask, acc[i], off));
            float xs = xsq_s[row];
            u64 bp = ~0ull;
            #pragma unroll
            for (int i = 0; i < 12; i++) {
                float dist = __fmaf_rn(-2.0f, acc[i],
                                       __fadd_rn(xs, ysq_s[cidx[i]]));
                u64 p = pack_di(dist, cidx[i]);
                if (p < bp) bp = p;
            }
            widx = (int)(u32)bp;
        }
        if (part == 0) resk[row] = widx;
    }
    __syncthreads();

    // Phase 2: per-row outputs + segment accumulation. 4 threads per row.
    {
        int row = tid >> 2, part = tid & 3;
        size_t n = (size_t)row0 + row;
        int idx = resk[row];
        const float* wp  = emb + (size_t)idx * DFULL + part * 32;
        const float* zp  = (part < 2) ? (zr + n * DHALF + part * 32)
                                      : (zi + n * DHALF + (part - 2) * 32);
        float* dwp = g_dw + (size_t)idx * DFULL + part * 32;
        float* oz  = (part < 2) ? (o_zqr + n * DHALF + part * 32)
                                : (o_zqi + n * DHALF + (part - 2) * 32);
        float ls = 0.f;
        #pragma unroll
        for (int q = 0; q < 8; q++) {
            float4 zv4 = *(const float4*)(zp + q * 4);
            float4 o;
            #pragma unroll
            for (int e2 = 0; e2 < 4; e2++) {
                float zv = (&zv4.x)[e2];
                float wv = __ldg(wp + q * 4 + e2);
                float dv = __fsub_rn(wv, zv);
                ls = __fadd_rn(ls, __fmul_rn(dv, dv));
                (&o.x)[e2] = __fadd_rn(zv, dv);   // z + (z_q - z): straight-through
            }
            REDG_V4(dwp + q * 4, zv4);
            *(float4*)(oz + q * 4) = o;
        }
        ls = __fadd_rn(ls, __shfl_xor_sync(0xffffffffu, ls, 1));
        ls = __fadd_rn(ls, __shfl_xor_sync(0xffffffffu, ls, 2));
        if (part == 0) {
            o_loss[n] = __fmul_rn(0.25f, __fmul_rn(ls, (1.0f / 128.0f)));
            o_idx[n]  = (float)idx;
            atomicAdd(&g_nt[idx], 1.0f);
        }
    }
}

// ---------------------------------------------------------------------------
// Stage 2: EMA update, cluster-size normalization, entropy. 1 block x 512.
// ---------------------------------------------------------------------------
__global__ void vq_final(const float* __restrict__ ecs, const float* __restrict__ emaw,
                         float* __restrict__ o_ent, float* __restrict__ o_emb,
                         float* __restrict__ o_nc,  float* __restrict__ o_ema)
{
    __shared__ float red[512];
    int k = threadIdx.x;
    const float DEC = 0.99f;
    const float OM  = (float)(1.0 - 0.99);

    float ntv = g_nt[k];
    float nc  = __fadd_rn(__fmul_rn(ecs[k], DEC), __fmul_rn(OM, ntv));
    o_nc[k] = nc;

    red[k] = nc;
    __syncthreads();
    for (int s = 256; s > 0; s >>= 1) {
        if (k < s) red[k] = __fadd_rn(red[k], red[k + s]);
        __syncthreads();
    }
    float tot = red[0];
    __syncthreads();

    float csz = __fmul_rn(__fdiv_rn(__fadd_rn(nc, 1e-5f),
                                    __fadd_rn(tot, (float)(512 * 1e-5))), tot);

    for (int d = 0; d < DFULL; d++) {
        float ne = __fadd_rn(__fmul_rn(emaw[(size_t)k * DFULL + d], DEC),
                             __fmul_rn(OM, g_dw[(size_t)k * DFULL + d]));
        o_ema[(size_t)k * DFULL + d] = ne;
        o_emb[(size_t)k * DFULL + d] = __fdiv_rn(ne, csz);
    }

    float p = __fdiv_rn(ntv, 262144.0f);
    float t = __fmul_rn(p, logf(__fadd_rn(p, 1e-10f)));
    red[k] = t;
    __syncthreads();
    for (int s = 256; s > 0; s >>= 1) {
        if (k < s) red[k] = __fadd_rn(red[k], red[k + s]);
        __syncthreads();
    }
    if (k == 0) o_ent[0] = __fdiv_rn(-red[0], 6.2383246250395075f);  // / log(512)
}

// ---------------------------------------------------------------------------
extern "C" void kernel_launch(void* const* d_in, const int* in_sizes, int n_in,
                              void* d_out, int out_size)
{
    const float* zr   = (const float*)d_in[0];
    const float* zi   = (const float*)d_in[1];
    const float* emb  = (const float*)d_in[2];
    const float* ecs  = (const float*)d_in[3];
    const float* emaw = (const float*)d_in[4];
    float* out = (float*)d_out;

    size_t nrows = (size_t)in_sizes[0] / DHALF;   // 262144

    // Output layout = reference return tuple, flattened + concatenated
    float* o_zqr  = out;
    float* o_zqi  = o_zqr + nrows * DHALF;
    float* o_loss = o_zqi + nrows * DHALF;
    float* o_idx  = o_loss + nrows;
    float* o_ent  = o_idx + nrows;
    float* o_emb  = o_ent + 1;
    float* o_nc   = o_emb + (size_t)KCODES * DFULL;
    float* o_ema  = o_nc + KCODES;

    vq_prep<<<KCODES, DFULL>>>(emb);

    cudaFuncSetAttribute(vq_main, cudaFuncAttributeMaxDynamicSharedMemorySize,
                         SM_TOTAL);
    vq_main<<<(unsigned)(nrows / MTILE), NTHREADS, SM_TOTAL>>>(
        zr, zi, emb, o_zqr, o_zqi, o_loss, o_idx);

    vq_final<<<1, 512>>>(ecs, emaw, o_ent, o_emb, o_nc, o_ema);
}

// round 15
// speedup vs baseline: 1.6746x; 1.1008x over previous
#include <cuda_runtime.h>
#include <cuda_fp16.h>
#include <cstdint>
#include <cfloat>
#include <math.h>

typedef unsigned long long u64;
typedef unsigned int u32;

#define DHALF 64
#define DFULL 128
#define KCODES 512
#define MTILE 128
#define NTHREADS 512

// Device-global scratch (allocation-free per harness rules)
__device__ float g_nt[KCODES];
__device__ float g_dw[KCODES * DFULL];
__device__ float g_ysq[KCODES];
__device__ __half g_hw[KCODES * DFULL];   // fp16 codebook, pre-scaled by 512

// ---------------------------------------------------------------------------
// Warp-level primitives (plain sm_80+ PTX; compute_103-safe)
// ---------------------------------------------------------------------------
__device__ __forceinline__ u32 smem_u32(const void* p) {
    u32 a;
    asm("{ .reg .u64 t; cvta.to.shared.u64 t, %1; cvt.u32.u64 %0, t; }"
        : "=r"(a) : "l"(p));
    return a;
}

#define LDSM_X4(r, addr) \
    asm volatile("ldmatrix.sync.aligned.m8n8.x4.shared.b16 {%0,%1,%2,%3}, [%4];" \
                 : "=r"((r)[0]), "=r"((r)[1]), "=r"((r)[2]), "=r"((r)[3]) \
                 : "r"(addr))

#define MMA16816F16(d, a, b0, b1) \
    asm volatile("mma.sync.aligned.m16n8k16.row.col.f32.f16.f16.f32 " \
                 "{%0,%1,%2,%3},{%4,%5,%6,%7},{%8,%9},{%0,%1,%2,%3};" \
                 : "+f"((d)[0]), "+f"((d)[1]), "+f"((d)[2]), "+f"((d)[3]) \
                 : "r"((a)[0]), "r"((a)[1]), "r"((a)[2]), "r"((a)[3]), \
                   "r"(b0), "r"(b1))

#define REDG_V4(ptr, v) \
    asm volatile("red.global.add.v4.f32 [%0], {%1,%2,%3,%4};" \
                 :: "l"(ptr), "f"((v).x), "f"((v).y), "f"((v).z), "f"((v).w) \
                 : "memory")

// Sortable-float transform (ascending u32 order == ascending float order)
__device__ __forceinline__ u32 fsort(float f) {
    u32 fb = __float_as_uint(f);
    return fb ^ ((u32)((int)fb >> 31) | 0x80000000u);
}
__device__ __forceinline__ float funsort(u32 k) {
    u32 fb = (k & 0x80000000u) ? (k ^ 0x80000000u) : ~k;
    return __uint_as_float(fb);
}
// Branchless insert into ascending-sorted u32 triple (IMNMX only, no branches)
__device__ __forceinline__ void ins3u(u32* t, u32 x) {
    u32 a = min(t[0], x), b = max(t[0], x); t[0] = a;
    u32 c = min(t[1], b), e = max(t[1], b); t[1] = c;
    t[2] = min(t[2], e);
}

// ---------------------------------------------------------------------------
// Stage 0: y_sq (reference fp32 order), zero accumulators, fp16 codebook
// pre-scaled by 512 (exact pow2; 512*w in (-1,1) -> fp16 rel err 2^-11).
// ---------------------------------------------------------------------------
__global__ void vq_prep(const float* __restrict__ emb) {
    int b = blockIdx.x, t = threadIdx.x;
    size_t e = (size_t)b * DFULL + t;
    float f = emb[e];
    g_hw[e] = __float2half_rn(__fmul_rn(f, 512.0f));
    g_dw[e] = 0.f;
    if (t == 0) {
        g_nt[b] = 0.f;
        const float* w = emb + (size_t)b * DFULL;
        float s = 0.f;
        #pragma unroll 8
        for (int d = 0; d < DFULL; d++) s = __fadd_rn(s, __fmul_rn(w[d], w[d]));
        g_ysq[b] = s;
    }
}

// ---------------------------------------------------------------------------
// Smem layout. A/B tiles: XOR-swizzled 8x8-atom layout. Atom (r8, katom) of a
// 128x128 fp16 tile at ((r8*16 + katom)*128) bytes; row r within the atom at
// 16B slot ((r&7) ^ (katom&7)) -> conflict-free ldmatrix AND conflict-free
// 16B-chunk stores (bank group now varies with katom).
// ---------------------------------------------------------------------------
static constexpr int SM_TOP3 = 0;        // 128 rows x 4 quads x 3 u32 = 6144
static constexpr int SM_XSQ  = 6144;     // 128 f32
static constexpr int SM_YSQ  = 6656;     // 512 f32
static constexpr int SM_RESK = 8704;     // 128 int
static constexpr int SM_A    = 16384;    // 32768 (128x128 fp16)
static constexpr int SM_B    = 49152;    // 32768 (128-code chunk fp16)
static constexpr int SM_TOTAL = 81920;

// ---------------------------------------------------------------------------
// Stage 1: single-term fp16 HMMA filter -> register-persistent top-3 per
// (row, quadrant) -> exact fp32 rescore (near-tie rows only) -> outputs +
// segment sums. One CTA per 128-row tile; 512 threads = 16 warps (4m x 4n).
// ---------------------------------------------------------------------------
__global__ void __launch_bounds__(NTHREADS, 1)
vq_main(const float* __restrict__ zr, const float* __restrict__ zi,
        const float* __restrict__ emb,
        float* __restrict__ o_zqr, float* __restrict__ o_zqi,
        float* __restrict__ o_loss, float* __restrict__ o_idx)
{
    extern __shared__ char sm[];
    const u32 smb = smem_u32(sm);
    const int tid  = threadIdx.x;
    const int wid  = tid >> 5, lane = tid & 31;
    const int wm   = wid & 3,  wn   = wid >> 2;
    const int row0 = blockIdx.x * MTILE;

    u32*   top3  = (u32*)(sm + SM_TOP3);
    float* xsq_s = (float*)(sm + SM_XSQ);
    float* ysq_s = (float*)(sm + SM_YSQ);
    int*   resk  = (int*)(sm + SM_RESK);

    if (tid < KCODES) ysq_s[tid] = g_ysq[tid];

    // A tile: z rows (real -> k 0-63, imag -> k 64-127) as fp16, swizzled
    // atom layout. katom = q>>1; slot xor key = katom&7.
    for (int i = tid; i < MTILE * 32; i += NTHREADS) {
        int row = i >> 5, q = i & 31;
        const float* src = (q < 16) ? (zr + (size_t)(row0 + row) * DHALF + q * 4)
                                    : (zi + (size_t)(row0 + row) * DHALF + (q - 16) * 4);
        float4 v = *(const float4*)src;
        int katom = q >> 1;
        u32 off = (u32)(((row >> 3) * 16 + katom) * 128
                        + (((row & 7) ^ (katom & 7)) * 16) + (q & 1) * 8);
        unsigned short h[4];
        #pragma unroll
        for (int e2 = 0; e2 < 4; e2++)
            h[e2] = __half_as_ushort(__float2half_rn((&v.x)[e2]));
        *(u64*)(sm + SM_A + off) = (u64)h[0] | ((u64)h[1] << 16)
                                 | ((u64)h[2] << 32) | ((u64)h[3] << 48);
    }

    // x_sq per row: sequential fp32 in reference order (real then imag)
    if (tid < MTILE) {
        const float* a = zr + (size_t)(row0 + tid) * DHALF;
        const float* b = zi + (size_t)(row0 + tid) * DHALF;
        float s = 0.f;
        #pragma unroll 8
        for (int d = 0; d < DHALF; d++) s = __fadd_rn(s, __fmul_rn(a[d], a[d]));
        #pragma unroll 8
        for (int d = 0; d < DHALF; d++) s = __fadd_rn(s, __fmul_rn(b[d], b[d]));
        xsq_s[tid] = s;
    }

    // Per-lane ldmatrix address pieces (xor-swizzle aware).
    const int l7 = lane & 7;
    const int a_mb = (lane >> 3) & 1;        // A: m+8 selector
    const int a_kb = (lane >> 4) & 1;        // A: k-atom parity
    const u32 ra16 = (u32)((l7 ^ a_kb) * 16);
    const u32 Apre = smb + SM_A + wm * 8192 + a_mb * 2048 + a_kb * 128;
    const int b_kb = (lane >> 3) & 1;        // B: k-atom parity
    const int b_nb = (lane >> 4) & 1;        // B: n+8 selector
    const u32 rb16 = (u32)((l7 ^ b_kb) * 16);
    const u32 Bpre = smb + SM_B + wn * 8192 + b_nb * 2048 + b_kb * 128;
    const int l4 = lane >> 2, lc = (lane & 3) * 2;

    // Register-persistent top-3 triples, one per (mt, rh) row-group.
    u32 trip[4][3];
    #pragma unroll
    for (int gi = 0; gi < 4; gi++)
        trip[gi][0] = trip[gi][1] = trip[gi][2] = 0xFFFFFFFFu;

    for (int c = 0; c < 4; c++) {
        __syncthreads();   // prior chunk's LDSM done before B overwrite

        // Load B chunk: 128 codes x 128 fp16 (pre-scaled), swizzled atoms.
        for (int i = tid; i < 128 * 16; i += NTHREADS) {
            int r = i >> 4, k16 = i & 15;
            const uint4 v = *(const uint4*)((const char*)g_hw
                + ((size_t)(c * 128 + r) * DFULL + (size_t)k16 * 8) * 2);
            *(uint4*)(sm + SM_B + ((r >> 3) * 16 + k16) * 128
                      + (((r & 7) ^ (k16 & 7)) * 16)) = v;
        }
        __syncthreads();

        float d[2][4][4];
        #pragma unroll
        for (int mt = 0; mt < 2; mt++)
            #pragma unroll
            for (int nt = 0; nt < 4; nt++)
                #pragma unroll
                for (int e2 = 0; e2 < 4; e2++) d[mt][nt][e2] = 0.f;

        #pragma unroll
        for (int ks = 0; ks < 8; ks++) {
            const u32 c16 = (u32)((ks & 3) * 32);   // ((2ks)&7)*16
            u32 a0[4], a1[4], t0[4], t1[4];
            u32 Aad = Apre + ks * 256 + (ra16 ^ c16);
            u32 Bad = Bpre + ks * 256 + (rb16 ^ c16);
            LDSM_X4(a0, Aad);
            LDSM_X4(a1, Aad + 4096);
            LDSM_X4(t0, Bad);           // nt 0,1
            LDSM_X4(t1, Bad + 4096);    // nt 2,3
            MMA16816F16(d[0][0], a0, t0[0], t0[1]);
            MMA16816F16(d[0][1], a0, t0[2], t0[3]);
            MMA16816F16(d[0][2], a0, t1[0], t1[1]);
            MMA16816F16(d[0][3], a0, t1[2], t1[3]);
            MMA16816F16(d[1][0], a1, t0[0], t0[1]);
            MMA16816F16(d[1][1], a1, t0[2], t0[3]);
            MMA16816F16(d[1][2], a1, t1[0], t1[1]);
            MMA16816F16(d[1][3], a1, t1[2], t1[3]);
        }

        // Chunk epilogue: dist' = 256*y_sq - d  (= 256*(dist - x_sq), x_sq
        // constant per row -> order-preserving). Quantized sortable key with
        // the 9-bit code in the low bits; branchless triple insert.
        #pragma unroll
        for (int mt = 0; mt < 2; mt++) {
            #pragma unroll
            for (int rh = 0; rh < 2; rh++) {
                u32* t = trip[mt * 2 + rh];
                #pragma unroll
                for (int nt = 0; nt < 4; nt++) {
                    #pragma unroll
                    for (int cl = 0; cl < 2; cl++) {
                        int code = c * 128 + wn * 32 + nt * 8 + lc + cl;
                        float dp = __fmaf_rn(256.0f, ysq_s[code],
                                             -d[mt][nt][rh * 2 + cl]);
                        ins3u(t, (fsort(dp) & 0xFFFFFE00u) | (u32)code);
                    }
                }
            }
        }
    }

    // Final merge: shfl across the 4 lanes sharing a row, owner writes smem.
    #pragma unroll
    for (int gi = 0; gi < 4; gi++) {
        u32 t[3] = {trip[gi][0], trip[gi][1], trip[gi][2]};
        #pragma unroll
        for (int off = 1; off <= 2; off <<= 1) {
            u32 o0 = __shfl_xor_sync(0xffffffffu, t[0], off);
            u32 o1 = __shfl_xor_sync(0xffffffffu, t[1], off);
            u32 o2 = __shfl_xor_sync(0xffffffffu, t[2], off);
            ins3u(t, o0); ins3u(t, o1); ins3u(t, o2);
        }
        if ((lane & 3) == 0) {
            int row = wm * 32 + (gi >> 1) * 16 + (gi & 1) * 8 + l4;
            u32* s = &top3[(row * 4 + wn) * 3];
            s[0] = t[0]; s[1] = t[1]; s[2] = t[2];
        }
    }
    __syncthreads();

    // Decision phase: 4 threads per row. Accept the approx winner only when
    // the approx top-2 dist'-gap exceeds 0.256 (= 1e-3 in dist units, ~40x
    // the filter error: fp16 inputs ~2.4e-5 rms + 4e-6 key quantization).
    // Otherwise rescore all 12 candidates in exact fp32 and take the
    // lexicographic (dist, idx) min == jnp.argmin first-min semantics.
    {
        int row = tid >> 2, part = tid & 3;
        size_t n = (size_t)row0 + row;
        u32* slot = top3 + row * 12;
        u32 c0 = 0xFFFFFFFFu, c1 = 0xFFFFFFFFu;
        int cidx[12];
        #pragma unroll
        for (int i = 0; i < 12; i++) {
            u32 x = slot[i];
            cidx[i] = (int)(x & 511u);
            u32 a = min(c0, x), b = max(c0, x);
            c0 = a; c1 = min(c1, b);
        }
        int widx;
        float f0 = funsort(c0 & 0xFFFFFE00u);
        float f1 = funsort(c1 & 0xFFFFFE00u);
        if (__fsub_rn(f1, f0) > 0.256f) {
            widx = (int)(c0 & 511u);
        } else {
            const u32 gmask = 0xFu << (lane & 28);
            const float* zp = (part < 2) ? (zr + n * DHALF + part * 32)
                                         : (zi + n * DHALF + (part - 2) * 32);
            float acc[12];
            #pragma unroll
            for (int i = 0; i < 12; i++) acc[i] = 0.f;
            for (int dd = 0; dd < 32; dd++) {
                float zv = __ldg(zp + dd);
                #pragma unroll
                for (int i = 0; i < 12; i++)
                    acc[i] = __fmaf_rn(zv,
                        __ldg(emb + (size_t)cidx[i] * DFULL + part * 32 + dd),
                        acc[i]);
            }
            #pragma unroll
            for (int off = 1; off <= 2; off <<= 1)
                #pragma unroll
                for (int i = 0; i < 12; i++)
                    acc[i] = __fadd_rn(acc[i],
                                       __shfl_xor_sync(gmask, acc[i], off));
            float xs = xsq_s[row];
            u64 bp = ~0ull;
            #pragma unroll
            for (int i = 0; i < 12; i++) {
                float dist = __fmaf_rn(-2.0f, acc[i],
                                       __fadd_rn(xs, ysq_s[cidx[i]]));
                u64 p = ((u64)fsort(dist) << 32) | (u32)cidx[i];
                bp = min(bp, p);
            }
            widx = (int)(u32)(bp & 511u);
        }
        if (part == 0) resk[row] = widx;
    }
    __syncthreads();

    // Phase 2: per-row outputs + segment accumulation. 4 threads per row.
    {
        int row = tid >> 2, part = tid & 3;
        size_t n = (size_t)row0 + row;
        int idx = resk[row];
        const float* wp  = emb + (size_t)idx * DFULL + part * 32;
        const float* zp  = (part < 2) ? (zr + n * DHALF + part * 32)
                                      : (zi + n * DHALF + (part - 2) * 32);
        float* dwp = g_dw + (size_t)idx * DFULL + part * 32;
        float* oz  = (part < 2) ? (o_zqr + n * DHALF + part * 32)
                                : (o_zqi + n * DHALF + (part - 2) * 32);
        float ls = 0.f;
        #pragma unroll
        for (int q = 0; q < 8; q++) {
            float4 zv4 = *(const float4*)(zp + q * 4);
            float4 o;
            #pragma unroll
            for (int e2 = 0; e2 < 4; e2++) {
                float zv = (&zv4.x)[e2];
                float wv = __ldg(wp + q * 4 + e2);
                float dv = __fsub_rn(wv, zv);
                ls = __fadd_rn(ls, __fmul_rn(dv, dv));
                (&o.x)[e2] = __fadd_rn(zv, dv);   // z + (z_q - z): straight-through
            }
            REDG_V4(dwp + q * 4, zv4);
            *(float4*)(oz + q * 4) = o;
        }
        ls = __fadd_rn(ls, __shfl_xor_sync(0xffffffffu, ls, 1));
        ls = __fadd_rn(ls, __shfl_xor_sync(0xffffffffu, ls, 2));
        if (part == 0) {
            o_loss[n] = __fmul_rn(0.25f, __fmul_rn(ls, (1.0f / 128.0f)));
            o_idx[n]  = (float)idx;
            atomicAdd(&g_nt[idx], 1.0f);
        }
    }
}

// ---------------------------------------------------------------------------
// Stage 2: EMA update, cluster-size normalization, entropy. 1 block x 512.
// ---------------------------------------------------------------------------
__global__ void vq_final(const float* __restrict__ ecs, const float* __restrict__ emaw,
                         float* __restrict__ o_ent, float* __restrict__ o_emb,
                         float* __restrict__ o_nc,  float* __restrict__ o_ema)
{
    __shared__ float red[512];
    int k = threadIdx.x;
    const float DEC = 0.99f;
    const float OM  = (float)(1.0 - 0.99);

    float ntv = g_nt[k];
    float nc  = __fadd_rn(__fmul_rn(ecs[k], DEC), __fmul_rn(OM, ntv));
    o_nc[k] = nc;

    red[k] = nc;
    __syncthreads();
    for (int s = 256; s > 0; s >>= 1) {
        if (k < s) red[k] = __fadd_rn(red[k], red[k + s]);
        __syncthreads();
    }
    float tot = red[0];
    __syncthreads();

    float csz = __fmul_rn(__fdiv_rn(__fadd_rn(nc, 1e-5f),
                                    __fadd_rn(tot, (float)(512 * 1e-5))), tot);

    for (int d = 0; d < DFULL; d++) {
        float ne = __fadd_rn(__fmul_rn(emaw[(size_t)k * DFULL + d], DEC),
                             __fmul_rn(OM, g_dw[(size_t)k * DFULL + d]));
        o_ema[(size_t)k * DFULL + d] = ne;
        o_emb[(size_t)k * DFULL + d] = __fdiv_rn(ne, csz);
    }

    float p = __fdiv_rn(ntv, 262144.0f);
    float t = __fmul_rn(p, logf(__fadd_rn(p, 1e-10f)));
    red[k] = t;
    __syncthreads();
    for (int s = 256; s > 0; s >>= 1) {
        if (k < s) red[k] = __fadd_rn(red[k], red[k + s]);
        __syncthreads();
    }
    if (k == 0) o_ent[0] = __fdiv_rn(-red[0], 6.2383246250395075f);  // / log(512)
}

// ---------------------------------------------------------------------------
extern "C" void kernel_launch(void* const* d_in, const int* in_sizes, int n_in,
                              void* d_out, int out_size)
{
    const float* zr   = (const float*)d_in[0];
    const float* zi   = (const float*)d_in[1];
    const float* emb  = (const float*)d_in[2];
    const float* ecs  = (const float*)d_in[3];
    const float* emaw = (const float*)d_in[4];
    float* out = (float*)d_out;

    size_t nrows = (size_t)in_sizes[0] / DHALF;   // 262144

    // Output layout = reference return tuple, flattened + concatenated
    float* o_zqr  = out;
    float* o_zqi  = o_zqr + nrows * DHALF;
    float* o_loss = o_zqi + nrows * DHALF;
    float* o_idx  = o_loss + nrows;
    float* o_ent  = o_idx + nrows;
    float* o_emb  = o_ent + 1;
    float* o_nc   = o_emb + (size_t)KCODES * DFULL;
    float* o_ema  = o_nc + KCODES;

    vq_prep<<<KCODES, DFULL>>>(emb);

    cudaFuncSetAttribute(vq_main, cudaFuncAttributeMaxDynamicSharedMemorySize,
                         SM_TOTAL);
    vq_main<<<(unsigned)(nrows / MTILE), NTHREADS, SM_TOTAL>>>(
        zr, zi, emb, o_zqr, o_zqi, o_loss, o_idx);

    vq_final<<<1, 512>>>(ecs, emaw, o_ent, o_emb, o_nc, o_ema);
}

// round 16
// speedup vs baseline: 1.9454x; 1.1617x over previous
#include <cuda_runtime.h>
#include <cuda_fp16.h>
#include <cstdint>
#include <cfloat>
#include <math.h>

typedef unsigned long long u64;
typedef unsigned int u32;

#define DHALF 64
#define DFULL 128
#define KCODES 512
#define MTILE 64
#define NTHREADS 256

// Device-global scratch (allocation-free per harness rules)
__device__ float g_nt[KCODES];
__device__ float g_dw[KCODES * DFULL];
__device__ float g_ysq[KCODES];
__device__ __half g_hw[KCODES * DFULL];   // fp16 codebook, pre-scaled by 512

// ---------------------------------------------------------------------------
// Warp-level primitives (plain sm_80+ PTX; compute_103-safe)
// ---------------------------------------------------------------------------
__device__ __forceinline__ u32 smem_u32(const void* p) {
    u32 a;
    asm("{ .reg .u64 t; cvta.to.shared.u64 t, %1; cvt.u32.u64 %0, t; }"
        : "=r"(a) : "l"(p));
    return a;
}

#define LDSM_X4(r, addr) \
    asm volatile("ldmatrix.sync.aligned.m8n8.x4.shared.b16 {%0,%1,%2,%3}, [%4];" \
                 : "=r"((r)[0]), "=r"((r)[1]), "=r"((r)[2]), "=r"((r)[3]) \
                 : "r"(addr))

#define MMA16816F16(d, a, b0, b1) \
    asm volatile("mma.sync.aligned.m16n8k16.row.col.f32.f16.f16.f32 " \
                 "{%0,%1,%2,%3},{%4,%5,%6,%7},{%8,%9},{%0,%1,%2,%3};" \
                 : "+f"((d)[0]), "+f"((d)[1]), "+f"((d)[2]), "+f"((d)[3]) \
                 : "r"((a)[0]), "r"((a)[1]), "r"((a)[2]), "r"((a)[3]), \
                   "r"(b0), "r"(b1))

#define REDG_V4(ptr, v) \
    asm volatile("red.global.add.v4.f32 [%0], {%1,%2,%3,%4};" \
                 :: "l"(ptr), "f"((v).x), "f"((v).y), "f"((v).z), "f"((v).w) \
                 : "memory")

// Sortable-float transform (ascending u32 order == ascending float order)
__device__ __forceinline__ u32 fsort(float f) {
    u32 fb = __float_as_uint(f);
    return fb ^ ((u32)((int)fb >> 31) | 0x80000000u);
}
__device__ __forceinline__ float funsort(u32 k) {
    u32 fb = (k & 0x80000000u) ? (k ^ 0x80000000u) : ~k;
    return __uint_as_float(fb);
}
// Branchless insert into ascending-sorted u32 triple (IMNMX only, no branches)
__device__ __forceinline__ void ins3u(u32* t, u32 x) {
    u32 a = min(t[0], x), b = max(t[0], x); t[0] = a;
    u32 c = min(t[1], b), e = max(t[1], b); t[1] = c;
    t[2] = min(t[2], e);
}

// ---------------------------------------------------------------------------
// Stage 0: y_sq (reference fp32 order), zero accumulators, fp16 codebook
// pre-scaled by 512 (exact pow2; 512*w in (-1,1) -> fp16 rel err 2^-11).
// ---------------------------------------------------------------------------
__global__ void vq_prep(const float* __restrict__ emb) {
    int b = blockIdx.x, t = threadIdx.x;
    size_t e = (size_t)b * DFULL + t;
    float f = emb[e];
    g_hw[e] = __float2half_rn(__fmul_rn(f, 512.0f));
    g_dw[e] = 0.f;
    if (t == 0) {
        g_nt[b] = 0.f;
        const float* w = emb + (size_t)b * DFULL;
        float s = 0.f;
        #pragma unroll 8
        for (int d = 0; d < DFULL; d++) s = __fadd_rn(s, __fmul_rn(w[d], w[d]));
        g_ysq[b] = s;
    }
}

// ---------------------------------------------------------------------------
// Smem layout. A/B tiles: XOR-swizzled 8x8-atom layout. Atom (r8, katom) at
// ((r8*16 + katom)*128) bytes; row r within the atom at 16B slot
// ((r&7) ^ (katom&7)) -> conflict-free ldmatrix AND conflict-free stores.
// ---------------------------------------------------------------------------
static constexpr int SM_TOP3 = 0;        // 64 rows x 4 quads x 3 u32 = 3072
static constexpr int SM_XSQ  = 3072;     // 64 f32
static constexpr int SM_YSQ  = 3328;     // 512 f32
static constexpr int SM_RESK = 5376;     // 64 int
static constexpr int SM_A    = 8192;     // 16384 (64x128 fp16)
static constexpr int SM_B    = 24576;    // 32768 (128-code chunk fp16)
static constexpr int SM_TOTAL = 57344;   // -> 3 CTAs/SM (reg-bound)

// ---------------------------------------------------------------------------
// Stage 1: single-term fp16 HMMA filter -> register-persistent top-3 per
// (row, quadrant) -> exact fp32 rescore (near-tie rows only) -> outputs +
// segment sums. One CTA per 64-row tile; 256 threads = 8 warps (2m x 4n),
// 32x32 warp tiles. 3 CTAs/SM to overlap loads/sync/epilogue across CTAs.
// ---------------------------------------------------------------------------
__global__ void __launch_bounds__(NTHREADS, 3)
vq_main(const float* __restrict__ zr, const float* __restrict__ zi,
        const float* __restrict__ emb,
        float* __restrict__ o_zqr, float* __restrict__ o_zqi,
        float* __restrict__ o_loss, float* __restrict__ o_idx)
{
    extern __shared__ char sm[];
    const u32 smb = smem_u32(sm);
    const int tid  = threadIdx.x;
    const int wid  = tid >> 5, lane = tid & 31;
    const int wm   = wid & 1,  wn   = wid >> 1;
    const int row0 = blockIdx.x * MTILE;

    u32*   top3  = (u32*)(sm + SM_TOP3);
    float* xsq_s = (float*)(sm + SM_XSQ);
    float* ysq_s = (float*)(sm + SM_YSQ);
    int*   resk  = (int*)(sm + SM_RESK);

    #pragma unroll
    for (int i = tid; i < KCODES; i += NTHREADS) ysq_s[i] = g_ysq[i];

    // A tile: z rows (real -> k 0-63, imag -> k 64-127) as fp16, swizzled
    // atom layout. katom = q>>1; slot xor key = katom&7.
    for (int i = tid; i < MTILE * 32; i += NTHREADS) {
        int row = i >> 5, q = i & 31;
        const float* src = (q < 16) ? (zr + (size_t)(row0 + row) * DHALF + q * 4)
                                    : (zi + (size_t)(row0 + row) * DHALF + (q - 16) * 4);
        float4 v = *(const float4*)src;
        int katom = q >> 1;
        u32 off = (u32)(((row >> 3) * 16 + katom) * 128
                        + (((row & 7) ^ (katom & 7)) * 16) + (q & 1) * 8);
        unsigned short h[4];
        #pragma unroll
        for (int e2 = 0; e2 < 4; e2++)
            h[e2] = __half_as_ushort(__float2half_rn((&v.x)[e2]));
        *(u64*)(sm + SM_A + off) = (u64)h[0] | ((u64)h[1] << 16)
                                 | ((u64)h[2] << 32) | ((u64)h[3] << 48);
    }

    // x_sq per row: sequential fp32 in reference order (real then imag)
    if (tid < MTILE) {
        const float* a = zr + (size_t)(row0 + tid) * DHALF;
        const float* b = zi + (size_t)(row0 + tid) * DHALF;
        float s = 0.f;
        #pragma unroll 8
        for (int d = 0; d < DHALF; d++) s = __fadd_rn(s, __fmul_rn(a[d], a[d]));
        #pragma unroll 8
        for (int d = 0; d < DHALF; d++) s = __fadd_rn(s, __fmul_rn(b[d], b[d]));
        xsq_s[tid] = s;
    }

    // Per-lane ldmatrix address pieces (xor-swizzle aware).
    const int l7 = lane & 7;
    const int a_mb = (lane >> 3) & 1;        // A: m+8 selector
    const int a_kb = (lane >> 4) & 1;        // A: k-atom parity
    const u32 ra16 = (u32)((l7 ^ a_kb) * 16);
    const u32 Apre = smb + SM_A + wm * 8192 + a_mb * 2048 + a_kb * 128;
    const int b_kb = (lane >> 3) & 1;        // B: k-atom parity
    const int b_nb = (lane >> 4) & 1;        // B: n+8 selector
    const u32 rb16 = (u32)((l7 ^ b_kb) * 16);
    const u32 Bpre = smb + SM_B + wn * 8192 + b_nb * 2048 + b_kb * 128;
    const int l4 = lane >> 2, lc = (lane & 3) * 2;

    // Register-persistent top-3 triples, one per (mt, rh) row-group.
    u32 trip[4][3];
    #pragma unroll
    for (int gi = 0; gi < 4; gi++)
        trip[gi][0] = trip[gi][1] = trip[gi][2] = 0xFFFFFFFFu;

    for (int c = 0; c < 4; c++) {
        __syncthreads();   // prior chunk's LDSM done before B overwrite

        // Load B chunk: 128 codes x 128 fp16 (pre-scaled), swizzled atoms.
        for (int i = tid; i < 128 * 16; i += NTHREADS) {
            int r = i >> 4, k16 = i & 15;
            const uint4 v = *(const uint4*)((const char*)g_hw
                + ((size_t)(c * 128 + r) * DFULL + (size_t)k16 * 8) * 2);
            *(uint4*)(sm + SM_B + ((r >> 3) * 16 + k16) * 128
                      + (((r & 7) ^ (k16 & 7)) * 16)) = v;
        }
        __syncthreads();

        float d[2][4][4];
        #pragma unroll
        for (int mt = 0; mt < 2; mt++)
            #pragma unroll
            for (int nt = 0; nt < 4; nt++)
                #pragma unroll
                for (int e2 = 0; e2 < 4; e2++) d[mt][nt][e2] = 0.f;

        #pragma unroll
        for (int ks = 0; ks < 8; ks++) {
            const u32 c16 = (u32)((ks & 3) * 32);   // ((2ks)&7)*16
            u32 a0[4], a1[4], t0[4], t1[4];
            u32 Aad = Apre + ks * 256 + (ra16 ^ c16);
            u32 Bad = Bpre + ks * 256 + (rb16 ^ c16);
            LDSM_X4(a0, Aad);
            LDSM_X4(a1, Aad + 4096);
            LDSM_X4(t0, Bad);           // nt 0,1
            LDSM_X4(t1, Bad + 4096);    // nt 2,3
            MMA16816F16(d[0][0], a0, t0[0], t0[1]);
            MMA16816F16(d[0][1], a0, t0[2], t0[3]);
            MMA16816F16(d[0][2], a0, t1[0], t1[1]);
            MMA16816F16(d[0][3], a0, t1[2], t1[3]);
            MMA16816F16(d[1][0], a1, t0[0], t0[1]);
            MMA16816F16(d[1][1], a1, t0[2], t0[3]);
            MMA16816F16(d[1][2], a1, t1[0], t1[1]);
            MMA16816F16(d[1][3], a1, t1[2], t1[3]);
        }

        // Chunk epilogue: dist' = 256*y_sq - d  (= 256*(dist - x_sq), x_sq
        // constant per row -> order-preserving). Quantized sortable key with
        // the 9-bit code in the low bits; branchless triple insert.
        #pragma unroll
        for (int mt = 0; mt < 2; mt++) {
            #pragma unroll
            for (int rh = 0; rh < 2; rh++) {
                u32* t = trip[mt * 2 + rh];
                #pragma unroll
                for (int nt = 0; nt < 4; nt++) {
                    #pragma unroll
                    for (int cl = 0; cl < 2; cl++) {
                        int code = c * 128 + wn * 32 + nt * 8 + lc + cl;
                        float dp = __fmaf_rn(256.0f, ysq_s[code],
                                             -d[mt][nt][rh * 2 + cl]);
                        ins3u(t, (fsort(dp) & 0xFFFFFE00u) | (u32)code);
                    }
                }
            }
        }
    }

    // Final merge: shfl across the 4 lanes sharing a row, owner writes smem.
    #pragma unroll
    for (int gi = 0; gi < 4; gi++) {
        u32 t[3] = {trip[gi][0], trip[gi][1], trip[gi][2]};
        #pragma unroll
        for (int off = 1; off <= 2; off <<= 1) {
            u32 o0 = __shfl_xor_sync(0xffffffffu, t[0], off);
            u32 o1 = __shfl_xor_sync(0xffffffffu, t[1], off);
            u32 o2 = __shfl_xor_sync(0xffffffffu, t[2], off);
            ins3u(t, o0); ins3u(t, o1); ins3u(t, o2);
        }
        if ((lane & 3) == 0) {
            int row = wm * 32 + (gi >> 1) * 16 + (gi & 1) * 8 + l4;
            u32* s = &top3[(row * 4 + wn) * 3];
            s[0] = t[0]; s[1] = t[1]; s[2] = t[2];
        }
    }
    __syncthreads();

    // Decision phase: 4 threads per row. Accept the approx winner only when
    // the approx top-2 dist'-gap exceeds 0.256 (= 1e-3 in dist units, ~40x
    // the filter error: fp16 inputs ~2.4e-5 rms + 4e-6 key quantization).
    // Otherwise rescore all 12 candidates in exact fp32 and take the
    // lexicographic (dist, idx) min == jnp.argmin first-min semantics.
    {
        int row = tid >> 2, part = tid & 3;
        size_t n = (size_t)row0 + row;
        u32* slot = top3 + row * 12;
        u32 c0 = 0xFFFFFFFFu, c1 = 0xFFFFFFFFu;
        int cidx[12];
        #pragma unroll
        for (int i = 0; i < 12; i++) {
            u32 x = slot[i];
            cidx[i] = (int)(x & 511u);
            u32 a = min(c0, x), b = max(c0, x);
            c0 = a; c1 = min(c1, b);
        }
        int widx;
        float f0 = funsort(c0 & 0xFFFFFE00u);
        float f1 = funsort(c1 & 0xFFFFFE00u);
        if (__fsub_rn(f1, f0) > 0.256f) {
            widx = (int)(c0 & 511u);
        } else {
            const u32 gmask = 0xFu << (lane & 28);
            const float* zp = (part < 2) ? (zr + n * DHALF + part * 32)
                                         : (zi + n * DHALF + (part - 2) * 32);
            float acc[12];
            #pragma unroll
            for (int i = 0; i < 12; i++) acc[i] = 0.f;
            for (int dd = 0; dd < 32; dd++) {
                float zv = __ldg(zp + dd);
                #pragma unroll
                for (int i = 0; i < 12; i++)
                    acc[i] = __fmaf_rn(zv,
                        __ldg(emb + (size_t)cidx[i] * DFULL + part * 32 + dd),
                        acc[i]);
            }
            #pragma unroll
            for (int off = 1; off <= 2; off <<= 1)
                #pragma unroll
                for (int i = 0; i < 12; i++)
                    acc[i] = __fadd_rn(acc[i],
                                       __shfl_xor_sync(gmask, acc[i], off));
            float xs = xsq_s[row];
            u64 bp = ~0ull;
            #pragma unroll
            for (int i = 0; i < 12; i++) {
                float dist = __fmaf_rn(-2.0f, acc[i],
                                       __fadd_rn(xs, ysq_s[cidx[i]]));
                u64 p = ((u64)fsort(dist) << 32) | (u32)cidx[i];
                bp = min(bp, p);
            }
            widx = (int)(u32)(bp & 511u);
        }
        if (part == 0) resk[row] = widx;
    }
    __syncthreads();

    // Phase 2: per-row outputs + segment accumulation. 4 threads per row.
    {
        int row = tid >> 2, part = tid & 3;
        size_t n = (size_t)row0 + row;
        int idx = resk[row];
        const float* wp  = emb + (size_t)idx * DFULL + part * 32;
        const float* zp  = (part < 2) ? (zr + n * DHALF + part * 32)
                                      : (zi + n * DHALF + (part - 2) * 32);
        float* dwp = g_dw + (size_t)idx * DFULL + part * 32;
        float* oz  = (part < 2) ? (o_zqr + n * DHALF + part * 32)
                                : (o_zqi + n * DHALF + (part - 2) * 32);
        float ls = 0.f;
        #pragma unroll
        for (int q = 0; q < 8; q++) {
            float4 zv4 = *(const float4*)(zp + q * 4);
            float4 o;
            #pragma unroll
            for (int e2 = 0; e2 < 4; e2++) {
                float zv = (&zv4.x)[e2];
                float wv = __ldg(wp + q * 4 + e2);
                float dv = __fsub_rn(wv, zv);
                ls = __fadd_rn(ls, __fmul_rn(dv, dv));
                (&o.x)[e2] = __fadd_rn(zv, dv);   // z + (z_q - z): straight-through
            }
            REDG_V4(dwp + q * 4, zv4);
            *(float4*)(oz + q * 4) = o;
        }
        ls = __fadd_rn(ls, __shfl_xor_sync(0xffffffffu, ls, 1));
        ls = __fadd_rn(ls, __shfl_xor_sync(0xffffffffu, ls, 2));
        if (part == 0) {
            o_loss[n] = __fmul_rn(0.25f, __fmul_rn(ls, (1.0f / 128.0f)));
            o_idx[n]  = (float)idx;
            atomicAdd(&g_nt[idx], 1.0f);
        }
    }
}

// ---------------------------------------------------------------------------
// Stage 2: EMA update, cluster-size normalization, entropy. 1 block x 512.
// ---------------------------------------------------------------------------
__global__ void vq_final(const float* __restrict__ ecs, const float* __restrict__ emaw,
                         float* __restrict__ o_ent, float* __restrict__ o_emb,
                         float* __restrict__ o_nc,  float* __restrict__ o_ema)
{
    __shared__ float red[512];
    int k = threadIdx.x;
    const float DEC = 0.99f;
    const float OM  = (float)(1.0 - 0.99);

    float ntv = g_nt[k];
    float nc  = __fadd_rn(__fmul_rn(ecs[k], DEC), __fmul_rn(OM, ntv));
    o_nc[k] = nc;

    red[k] = nc;
    __syncthreads();
    for (int s = 256; s > 0; s >>= 1) {
        if (k < s) red[k] = __fadd_rn(red[k], red[k + s]);
        __syncthreads();
    }
    float tot = red[0];
    __syncthreads();

    float csz = __fmul_rn(__fdiv_rn(__fadd_rn(nc, 1e-5f),
                                    __fadd_rn(tot, (float)(512 * 1e-5))), tot);

    for (int d = 0; d < DFULL; d++) {
        float ne = __fadd_rn(__fmul_rn(emaw[(size_t)k * DFULL + d], DEC),
                             __fmul_rn(OM, g_dw[(size_t)k * DFULL + d]));
        o_ema[(size_t)k * DFULL + d] = ne;
        o_emb[(size_t)k * DFULL + d] = __fdiv_rn(ne, csz);
    }

    float p = __fdiv_rn(ntv, 262144.0f);
    float t = __fmul_rn(p, logf(__fadd_rn(p, 1e-10f)));
    red[k] = t;
    __syncthreads();
    for (int s = 256; s > 0; s >>= 1) {
        if (k < s) red[k] = __fadd_rn(red[k], red[k + s]);
        __syncthreads();
    }
    if (k == 0) o_ent[0] = __fdiv_rn(-red[0], 6.2383246250395075f);  // / log(512)
}

// ---------------------------------------------------------------------------
extern "C" void kernel_launch(void* const* d_in, const int* in_sizes, int n_in,
                              void* d_out, int out_size)
{
    const float* zr   = (const float*)d_in[0];
    const float* zi   = (const float*)d_in[1];
    const float* emb  = (const float*)d_in[2];
    const float* ecs  = (const float*)d_in[3];
    const float* emaw = (const float*)d_in[4];
    float* out = (float*)d_out;

    size_t nrows = (size_t)in_sizes[0] / DHALF;   // 262144

    // Output layout = reference return tuple, flattened + concatenated
    float* o_zqr  = out;
    float* o_zqi  = o_zqr + nrows * DHALF;
    float* o_loss = o_zqi + nrows * DHALF;
    float* o_idx  = o_loss + nrows;
    float* o_ent  = o_idx + nrows;
    float* o_emb  = o_ent + 1;
    float* o_nc   = o_emb + (size_t)KCODES * DFULL;
    float* o_ema  = o_nc + KCODES;

    vq_prep<<<KCODES, DFULL>>>(emb);

    cudaFuncSetAttribute(vq_main, cudaFuncAttributeMaxDynamicSharedMemorySize,
                         SM_TOTAL);
    vq_main<<<(unsigned)(nrows / MTILE), NTHREADS, SM_TOTAL>>>(
        zr, zi, emb, o_zqr, o_zqi, o_loss, o_idx);

    vq_final<<<1, 512>>>(ecs, emaw, o_ent, o_emb, o_nc, o_ema);
}